// round 14
// baseline (speedup 1.0000x reference)
#include <cuda_runtime.h>
#include <cuda_fp16.h>
#include <math.h>
#include <stdint.h>

#define NN 20000
#define EE 320000
#define DD 256
#define HH 8
#define KD 32
#define TT 3
#define RR 5
#define CC 16

// ---------------- scratch (static device globals; no allocation) ----------
__device__ __half g_Kn[NN * DD];                 // fp16 keys
__device__ float  g_Qn[NN * DD];                 // fp32 queries
__device__ float  g_Vn[NN * DD];                 // fp32 values
__device__ __half g_Qt[(size_t)RR * NN * DD];    // prior/sqrtK * rel_att^T . Q
__device__ __half g_MtN[(size_t)RR * NN * DD];   // rel_msg transform of V
__device__ float  g_aggr[NN * DD];
__device__ float  g_hbuf[NN * DD];
__device__ int    g_order[NN];
__device__ int    g_cnt[TT];
__device__ int    g_base[TT];
__device__ int    g_deg[NN];      // zero at load; re-zeroed by k_scanE
__device__ int    g_start[NN + 1];
__device__ int    g_cur2[NN];
__device__ int    g_epack[EE];    // src | (r << 24), sorted by dst

// ---------------- side stream + events for graph fork/join ------------------
static cudaStream_t g_s2;
static cudaEvent_t  g_evFork, g_evJoin;
static const bool g_side_init = [] {
    cudaStreamCreateWithFlags(&g_s2, cudaStreamNonBlocking);
    cudaEventCreateWithFlags(&g_evFork, cudaEventDisableTiming);
    cudaEventCreateWithFlags(&g_evJoin, cudaEventDisableTiming);
    return true;
}();

// ---------------- helpers --------------------------------------------------
__device__ __forceinline__ void mma_f16(float* d, const uint32_t* a,
                                        const uint32_t* b) {
    asm volatile(
        "mma.sync.aligned.m16n8k16.row.col.f32.f16.f16.f32 "
        "{%0,%1,%2,%3}, {%4,%5,%6,%7}, {%8,%9}, {%0,%1,%2,%3};\n"
        : "+f"(d[0]), "+f"(d[1]), "+f"(d[2]), "+f"(d[3])
        : "r"(a[0]), "r"(a[1]), "r"(a[2]), "r"(a[3]), "r"(b[0]), "r"(b[1]));
}

__device__ __forceinline__ uint32_t h2u(const __half2& h) {
    return *reinterpret_cast<const uint32_t*>(&h);
}

// ---------------- node bucketing: ONE single-block kernel -------------------
__global__ __launch_bounds__(1024) void k_nodeprep(const int* __restrict__ nt) {
    __shared__ int wsum[32][TT];
    __shared__ int cursor[TT];
    const int tid = threadIdx.x;
    const int lane = tid & 31, w = tid >> 5;

    // pass 1: per-thread counts, warp + block reduce
    int c0 = 0, c1 = 0, c2 = 0;
    for (int i = tid; i < NN; i += 1024) {
        int t = nt[i];
        c0 += (t == 0); c1 += (t == 1); c2 += (t == 2);
    }
#pragma unroll
    for (int off = 16; off; off >>= 1) {
        c0 += __shfl_xor_sync(0xffffffffu, c0, off);
        c1 += __shfl_xor_sync(0xffffffffu, c1, off);
        c2 += __shfl_xor_sync(0xffffffffu, c2, off);
    }
    if (lane == 0) { wsum[w][0] = c0; wsum[w][1] = c1; wsum[w][2] = c2; }
    __syncthreads();
    if (tid == 0) {
        int t0 = 0, t1 = 0, t2 = 0;
        for (int i = 0; i < 32; i++) {
            t0 += wsum[i][0]; t1 += wsum[i][1]; t2 += wsum[i][2];
        }
        g_cnt[0] = t0; g_cnt[1] = t1; g_cnt[2] = t2;
        g_base[0] = 0; g_base[1] = t0; g_base[2] = t0 + t1;
        cursor[0] = 0; cursor[1] = t0; cursor[2] = t0 + t1;
    }
    __syncthreads();

    // pass 2: scatter with warp-aggregated smem atomics
    for (int basei = 0; basei < NN; basei += 1024) {
        int i = basei + tid;
        int t = (i < NN) ? nt[i] : -1;
#pragma unroll
        for (int tt = 0; tt < TT; tt++) {
            unsigned m = __ballot_sync(0xffffffffu, t == tt);
            if (t == tt) {
                int leader = __ffs(m) - 1;
                int posbase = 0;
                if (lane == leader) posbase = atomicAdd(&cursor[tt], __popc(m));
                posbase = __shfl_sync(m, posbase, leader);
                int pos = posbase + __popc(m & ((1u << lane) - 1));
                g_order[pos] = i;
            }
        }
    }
}

// ---------------- edge-side setup (side stream) ------------------------------
__global__ void k_countE(const int* __restrict__ ei) {
    int i = blockIdx.x * blockDim.x + threadIdx.x;
    if (i < EE) atomicAdd(&g_deg[ei[EE + i]], 1);
}

__global__ __launch_bounds__(1024) void k_scanE() {
    __shared__ int part[1024];
    const int tid = threadIdx.x;
    const int CH = (NN + 1023) / 1024;
    int base = tid * CH;
    int s = 0;
    for (int j = 0; j < CH; j++)
        if (base + j < NN) s += g_deg[base + j];
    part[tid] = s;
    __syncthreads();
    for (int off = 1; off < 1024; off <<= 1) {
        int v = (tid >= off) ? part[tid - off] : 0;
        __syncthreads();
        part[tid] += v;
        __syncthreads();
    }
    int run = (tid == 0) ? 0 : part[tid - 1];
    for (int j = 0; j < CH; j++) {
        if (base + j < NN) {
            int d = g_deg[base + j];
            g_deg[base + j] = 0;          // re-zero for the next replay
            g_start[base + j] = run;
            g_cur2[base + j] = run;
            run += d;
        }
    }
    if (tid == 1023) g_start[NN] = part[1023];
}

__global__ void k_placeE(const int* __restrict__ ei,
                         const int* __restrict__ et) {
    int i = blockIdx.x * blockDim.x + threadIdx.x;
    if (i < EE) {
        int dst = ei[EE + i];
        int pos = atomicAdd(&g_cur2[dst], 1);
        g_epack[pos] = ei[i] | (et[i] << 24);
    }
}

// ---------------- typed (gathered) linear via fp16 mma ---------------------
// Smem tiles are __half2 with k-pairs packed (As[kp][m], Bs[kp][n]); one
// 32-bit LDS per fragment register, conversion done once at staging.
// MODE 0 : Out = X @ W[t] + b[t]
// MODE 3 : Out = elu(g_aggr) @ W[t] + b[t] + x  (residual, float out)
template <int MODE, typename OutT>
__device__ __forceinline__ void typed_gemm_body(
    const float* __restrict__ X, const float* __restrict__ Xres,
    const float* __restrict__ W, const float* __restrict__ bvec,
    OutT* __restrict__ Out, int t, int m0, int n0) {
    const int cnt = g_cnt[t];
    if (m0 >= cnt) return;
    const int base = g_base[t];
    const int tid = threadIdx.x;
    const int lane = tid & 31, wid = tid >> 5;
    const int wm = wid & 3, wn = wid >> 2;
    const int grp = lane >> 2, tig = lane & 3;

    __shared__ __half2 As[16][136];   // [kp][m], row stride 136 (%32 == 8)
    __shared__ __half2 Bs[16][72];    // [kp][n], row stride 72  (%32 == 8)

    const int arow = tid >> 1;
    const int kpbase = (tid & 1) * 8;
    const int acol0 = (tid & 1) * 16;
    const int am = m0 + arow;
    const float* aptr = nullptr;
    if (am < cnt) aptr = X + (size_t)g_order[base + am] * DD + acol0;

    const int bkp = tid >> 4;          // 0..15
    const int bnq = (tid & 15) * 4;    // 0..60

    float acc[2][4][4];
#pragma unroll
    for (int i = 0; i < 2; i++)
#pragma unroll
        for (int j = 0; j < 4; j++)
#pragma unroll
            for (int k = 0; k < 4; k++) acc[i][j][k] = 0.f;

    for (int kk = 0; kk < DD; kk += 32) {
#pragma unroll
        for (int j = 0; j < 4; j++) {
            float4 v = make_float4(0.f, 0.f, 0.f, 0.f);
            if (aptr) v = *reinterpret_cast<const float4*>(aptr + kk + j * 4);
            if (MODE == 3) {
                v.x = v.x > 0.f ? v.x : expm1f(v.x);
                v.y = v.y > 0.f ? v.y : expm1f(v.y);
                v.z = v.z > 0.f ? v.z : expm1f(v.z);
                v.w = v.w > 0.f ? v.w : expm1f(v.w);
            }
            As[kpbase + j * 2 + 0][arow] = __floats2half2_rn(v.x, v.y);
            As[kpbase + j * 2 + 1][arow] = __floats2half2_rn(v.z, v.w);
        }
        {
            float4 v0 = *reinterpret_cast<const float4*>(
                W + (size_t)(kk + 2 * bkp) * DD + n0 + bnq);
            float4 v1 = *reinterpret_cast<const float4*>(
                W + (size_t)(kk + 2 * bkp + 1) * DD + n0 + bnq);
            Bs[bkp][bnq + 0] = __floats2half2_rn(v0.x, v1.x);
            Bs[bkp][bnq + 1] = __floats2half2_rn(v0.y, v1.y);
            Bs[bkp][bnq + 2] = __floats2half2_rn(v0.z, v1.z);
            Bs[bkp][bnq + 3] = __floats2half2_rn(v0.w, v1.w);
        }
        __syncthreads();
#pragma unroll
        for (int ks = 0; ks < 2; ks++) {
            const int kp0 = ks * 8 + tig;
            uint32_t a[2][4], b[4][2];
#pragma unroll
            for (int mt = 0; mt < 2; mt++) {
                int mb = wm * 32 + mt * 16 + grp;
                a[mt][0] = h2u(As[kp0][mb]);
                a[mt][1] = h2u(As[kp0][mb + 8]);
                a[mt][2] = h2u(As[kp0 + 4][mb]);
                a[mt][3] = h2u(As[kp0 + 4][mb + 8]);
            }
#pragma unroll
            for (int nt = 0; nt < 4; nt++) {
                int nb = wn * 32 + nt * 8 + grp;
                b[nt][0] = h2u(Bs[kp0][nb]);
                b[nt][1] = h2u(Bs[kp0 + 4][nb]);
            }
#pragma unroll
            for (int mt = 0; mt < 2; mt++)
#pragma unroll
                for (int nt = 0; nt < 4; nt++)
                    mma_f16(acc[mt][nt], a[mt], b[nt]);
        }
        __syncthreads();
    }

#pragma unroll
    for (int mt = 0; mt < 2; mt++) {
        int mr0 = m0 + wm * 32 + mt * 16 + grp;
        int mr1 = mr0 + 8;
        int node0 = (mr0 < cnt) ? g_order[base + mr0] : -1;
        int node1 = (mr1 < cnt) ? g_order[base + mr1] : -1;
#pragma unroll
        for (int nt = 0; nt < 4; nt++) {
            int col = n0 + wn * 32 + nt * 8 + tig * 2;
            float2 bi = *reinterpret_cast<const float2*>(bvec + col);
            if (node0 >= 0) {
                float o0 = acc[mt][nt][0] + bi.x;
                float o1 = acc[mt][nt][1] + bi.y;
                if (MODE == 3) {
                    float2 rr = *reinterpret_cast<const float2*>(
                        Xres + (size_t)node0 * DD + col);
                    o0 += rr.x; o1 += rr.y;
                }
                OutT* dst = Out + (size_t)node0 * DD + col;
                if (sizeof(OutT) == 2)
                    *reinterpret_cast<__half2*>(dst) = __floats2half2_rn(o0, o1);
                else
                    *reinterpret_cast<float2*>(dst) = make_float2(o0, o1);
            }
            if (node1 >= 0) {
                float o0 = acc[mt][nt][2] + bi.x;
                float o1 = acc[mt][nt][3] + bi.y;
                if (MODE == 3) {
                    float2 rr = *reinterpret_cast<const float2*>(
                        Xres + (size_t)node1 * DD + col);
                    o0 += rr.x; o1 += rr.y;
                }
                OutT* dst = Out + (size_t)node1 * DD + col;
                if (sizeof(OutT) == 2)
                    *reinterpret_cast<__half2*>(dst) = __floats2half2_rn(o0, o1);
                else
                    *reinterpret_cast<float2*>(dst) = make_float2(o0, o1);
            }
        }
    }
}

// fused K/Q/V projection: grid.z = 3*TT (which = z/TT, t = z%TT)
__global__ __launch_bounds__(256) void k_typed_kqv(
    const float* __restrict__ x,
    const float* __restrict__ Wk, const float* __restrict__ bk,
    const float* __restrict__ Wq, const float* __restrict__ bq,
    const float* __restrict__ Wv, const float* __restrict__ bv) {
    const int z = blockIdx.z;
    const int which = z / TT;
    const int t = z % TT;
    if (which == 0)
        typed_gemm_body<0, __half>(x, nullptr, Wk + (size_t)t * DD * DD,
                                   bk + t * DD, g_Kn, t, blockIdx.x * 128,
                                   blockIdx.y * 64);
    else if (which == 1)
        typed_gemm_body<0, float>(x, nullptr, Wq + (size_t)t * DD * DD,
                                  bq + t * DD, g_Qn, t, blockIdx.x * 128,
                                  blockIdx.y * 64);
    else
        typed_gemm_body<0, float>(x, nullptr, Wv + (size_t)t * DD * DD,
                                  bv + t * DD, g_Vn, t, blockIdx.x * 128,
                                  blockIdx.y * 64);
}

// update: g_hbuf = elu(g_aggr) @ Wa[t] + ba[t] + x
__global__ __launch_bounds__(256) void k_typed_upd(
    const float* __restrict__ x, const float* __restrict__ Wa,
    const float* __restrict__ ba) {
    const int t = blockIdx.z;
    typed_gemm_body<3, float>(g_aggr, x, Wa + (size_t)t * DD * DD, ba + t * DD,
                              g_hbuf, t, blockIdx.x * 128, blockIdx.y * 64);
}

// ---------------- Qt / MtN transforms via fp16 mma, fp16 output -------------
// z=0: g_Qt [r,n,h,k] = prh * sum_l rel_att[r,h,k,l] * Qn[n,h,l]  (transposed B)
// z=1: g_MtN[r,n,h,l] = sum_k Vn[n,h,k] * rel_msg[r,h,k,l]        (natural B)
__global__ __launch_bounds__(256) void k_rel_mma(
    const float* __restrict__ rel_att, const float* __restrict__ rel_msg,
    const float* __restrict__ prior) {
    const int h = blockIdx.y;
    const int which = blockIdx.z;
    const float* In = which ? g_Vn : g_Qn;
    const float* Rel = which ? rel_msg : rel_att;
    __half* Out = which ? g_MtN : g_Qt;
    const int nbase = blockIdx.x * 128;
    const int tid = threadIdx.x;
    const int lane = tid & 31, wid = tid >> 5;
    const int wm = wid & 3, wn = wid >> 2;
    const int grp = lane >> 2, tig = lane & 3;

    __shared__ __half2 As[16][136];     // [kp][m]
    __shared__ __half2 Bs[5][16][40];   // [r][kp][n], row stride 40 (%32 == 8)

    {
        int arow = tid >> 1;
        int kpbase = (tid & 1) * 8;
        int acol0 = (tid & 1) * 16;
        int node = nbase + arow;
        const float* ap = (node < NN)
                              ? In + (size_t)node * DD + h * KD + acol0
                              : nullptr;
#pragma unroll
        for (int j = 0; j < 4; j++) {
            float4 v = ap ? *reinterpret_cast<const float4*>(ap + j * 4)
                          : make_float4(0.f, 0.f, 0.f, 0.f);
            As[kpbase + j * 2 + 0][arow] = __floats2half2_rn(v.x, v.y);
            As[kpbase + j * 2 + 1][arow] = __floats2half2_rn(v.z, v.w);
        }
        if (which == 0) {
#pragma unroll
            for (int j = 0; j < 5; j++) {
                int f = tid + j * 256;
                int r = f >> 8;
                int rem = f & 255;
                int k = rem >> 3, lq = (rem & 7) * 4;
                float4 v = *reinterpret_cast<const float4*>(
                    Rel + (size_t)(r * HH + h) * (KD * KD) + k * KD + lq);
                Bs[r][lq / 2 + 0][k] = __floats2half2_rn(v.x, v.y);
                Bs[r][lq / 2 + 1][k] = __floats2half2_rn(v.z, v.w);
            }
        } else {
            for (int f = tid; f < 640; f += 256) {
                int r = f >> 7;
                int rem = f & 127;
                int kp = rem >> 3, lq = (rem & 7) * 4;
                const float* rb =
                    Rel + (size_t)(r * HH + h) * (KD * KD) + (2 * kp) * KD + lq;
                float4 v0 = *reinterpret_cast<const float4*>(rb);
                float4 v1 = *reinterpret_cast<const float4*>(rb + KD);
                Bs[r][kp][lq + 0] = __floats2half2_rn(v0.x, v1.x);
                Bs[r][kp][lq + 1] = __floats2half2_rn(v0.y, v1.y);
                Bs[r][kp][lq + 2] = __floats2half2_rn(v0.z, v1.z);
                Bs[r][kp][lq + 3] = __floats2half2_rn(v0.w, v1.w);
            }
        }
    }
    __syncthreads();

    uint32_t a[2][2][4];
#pragma unroll
    for (int ks = 0; ks < 2; ks++) {
        int kp0 = ks * 8 + tig;
#pragma unroll
        for (int mt = 0; mt < 2; mt++) {
            int mb = wm * 32 + mt * 16 + grp;
            a[ks][mt][0] = h2u(As[kp0][mb]);
            a[ks][mt][1] = h2u(As[kp0][mb + 8]);
            a[ks][mt][2] = h2u(As[kp0 + 4][mb]);
            a[ks][mt][3] = h2u(As[kp0 + 4][mb + 8]);
        }
    }

    for (int r = 0; r < RR; r++) {
        const float scale =
            which ? 1.f : prior[r * HH + h] * 0.17677669529663688f;
        float acc[2][2][4];
#pragma unroll
        for (int i = 0; i < 2; i++)
#pragma unroll
            for (int j = 0; j < 2; j++)
#pragma unroll
                for (int k = 0; k < 4; k++) acc[i][j][k] = 0.f;
#pragma unroll
        for (int ks = 0; ks < 2; ks++) {
            int kp0 = ks * 8 + tig;
            uint32_t b[2][2];
#pragma unroll
            for (int nt = 0; nt < 2; nt++) {
                int nb = wn * 16 + nt * 8 + grp;
                b[nt][0] = h2u(Bs[r][kp0][nb]);
                b[nt][1] = h2u(Bs[r][kp0 + 4][nb]);
            }
#pragma unroll
            for (int mt = 0; mt < 2; mt++)
#pragma unroll
                for (int nt = 0; nt < 2; nt++)
                    mma_f16(acc[mt][nt], a[ks][mt], b[nt]);
        }
        __half* Or = Out + (size_t)r * NN * DD;
#pragma unroll
        for (int mt = 0; mt < 2; mt++) {
            int nr0 = nbase + wm * 32 + mt * 16 + grp;
            int nr1 = nr0 + 8;
#pragma unroll
            for (int nt = 0; nt < 2; nt++) {
                int col = h * KD + wn * 16 + nt * 8 + tig * 2;
                if (nr0 < NN)
                    *reinterpret_cast<__half2*>(Or + (size_t)nr0 * DD + col) =
                        __floats2half2_rn(acc[mt][nt][0] * scale,
                                          acc[mt][nt][1] * scale);
                if (nr1 < NN)
                    *reinterpret_cast<__half2*>(Or + (size_t)nr1 * DD + col) =
                        __floats2half2_rn(acc[mt][nt][2] * scale,
                                          acc[mt][nt][3] * scale);
            }
        }
    }
}

// ---------------- fused edge phase: one warp per destination ---------------
__global__ __launch_bounds__(256) void k_edge() {
    __shared__ __half sQt[8][RR][256];
    int gw = (blockIdx.x * 256 + threadIdx.x) >> 5;
    if (gw >= NN) return;
    const int w = (threadIdx.x >> 5) & 7;
    const int lane = threadIdx.x & 31;
    const int dst = gw;
    const int s0 = g_start[dst], s1 = g_start[dst + 1];

#pragma unroll
    for (int r = 0; r < RR; r++) {
        float4 q = __ldcs(reinterpret_cast<const float4*>(
            g_Qt + ((size_t)r * NN + dst) * DD + lane * 8));
        *reinterpret_cast<float4*>(&sQt[w][r][lane * 8]) = q;
    }
    // no sync: each lane reads only its own slot

    float ssA = 0.f, ssB = 0.f;
    float aA0 = 0.f, aA1 = 0.f, aA2 = 0.f, aA3 = 0.f;
    float aA4 = 0.f, aA5 = 0.f, aA6 = 0.f, aA7 = 0.f;
    float aB0 = 0.f, aB1 = 0.f, aB2 = 0.f, aB3 = 0.f;
    float aB4 = 0.f, aB5 = 0.f, aB6 = 0.f, aB7 = 0.f;

    int i = s0;
    for (; i + 2 <= s1; i += 2) {
        int pk0 = __ldcs(g_epack + i);
        int pk1 = __ldcs(g_epack + i + 1);
        int r0 = ((unsigned)pk0) >> 24, r1 = ((unsigned)pk1) >> 24;
        size_t ko0 = (size_t)(pk0 & 0xFFFFFF) * DD + lane * 8;
        size_t ko1 = (size_t)(pk1 & 0xFFFFFF) * DD + lane * 8;
        float4 kraw0 = *reinterpret_cast<const float4*>(g_Kn + ko0);
        float4 kraw1 = *reinterpret_cast<const float4*>(g_Kn + ko1);
        float4 mraw0 =
            *reinterpret_cast<const float4*>(g_MtN + (size_t)r0 * NN * DD + ko0);
        float4 mraw1 =
            *reinterpret_cast<const float4*>(g_MtN + (size_t)r1 * NN * DD + ko1);
        float4 qraw0 = *reinterpret_cast<const float4*>(&sQt[w][r0][lane * 8]);
        float4 qraw1 = *reinterpret_cast<const float4*>(&sQt[w][r1][lane * 8]);

        const __half2* qh0 = reinterpret_cast<const __half2*>(&qraw0);
        const __half2* qh1 = reinterpret_cast<const __half2*>(&qraw1);
        const __half2* kh0 = reinterpret_cast<const __half2*>(&kraw0);
        const __half2* kh1 = reinterpret_cast<const __half2*>(&kraw1);
        float d0 = 0.f, d1 = 0.f;
#pragma unroll
        for (int j = 0; j < 4; j++) {
            float2 q0 = __half22float2(qh0[j]);
            float2 k0 = __half22float2(kh0[j]);
            float2 q1 = __half22float2(qh1[j]);
            float2 k1 = __half22float2(kh1[j]);
            d0 += q0.x * k0.x + q0.y * k0.y;
            d1 += q1.x * k1.x + q1.y * k1.y;
        }
        d0 += __shfl_xor_sync(0xffffffffu, d0, 1);
        d1 += __shfl_xor_sync(0xffffffffu, d1, 1);
        d0 += __shfl_xor_sync(0xffffffffu, d0, 2);
        d1 += __shfl_xor_sync(0xffffffffu, d1, 2);
        float ex0 = __expf(d0);
        float ex1 = __expf(d1);
        ssA += ex0;
        ssB += ex1;
        const __half2* mh0 = reinterpret_cast<const __half2*>(&mraw0);
        const __half2* mh1 = reinterpret_cast<const __half2*>(&mraw1);
        float2 m00 = __half22float2(mh0[0]), m01 = __half22float2(mh0[1]);
        float2 m02 = __half22float2(mh0[2]), m03 = __half22float2(mh0[3]);
        float2 m10 = __half22float2(mh1[0]), m11 = __half22float2(mh1[1]);
        float2 m12 = __half22float2(mh1[2]), m13 = __half22float2(mh1[3]);
        aA0 += ex0 * m00.x; aA1 += ex0 * m00.y;
        aA2 += ex0 * m01.x; aA3 += ex0 * m01.y;
        aA4 += ex0 * m02.x; aA5 += ex0 * m02.y;
        aA6 += ex0 * m03.x; aA7 += ex0 * m03.y;
        aB0 += ex1 * m10.x; aB1 += ex1 * m10.y;
        aB2 += ex1 * m11.x; aB3 += ex1 * m11.y;
        aB4 += ex1 * m12.x; aB5 += ex1 * m12.y;
        aB6 += ex1 * m13.x; aB7 += ex1 * m13.y;
    }
    if (i < s1) {
        int pk = __ldcs(g_epack + i);
        int r = ((unsigned)pk) >> 24;
        size_t ko = (size_t)(pk & 0xFFFFFF) * DD + lane * 8;
        float4 kraw = *reinterpret_cast<const float4*>(g_Kn + ko);
        float4 mraw =
            *reinterpret_cast<const float4*>(g_MtN + (size_t)r * NN * DD + ko);
        float4 qraw = *reinterpret_cast<const float4*>(&sQt[w][r][lane * 8]);
        const __half2* qh = reinterpret_cast<const __half2*>(&qraw);
        const __half2* kh = reinterpret_cast<const __half2*>(&kraw);
        float d = 0.f;
#pragma unroll
        for (int j = 0; j < 4; j++) {
            float2 q = __half22float2(qh[j]);
            float2 k = __half22float2(kh[j]);
            d += q.x * k.x + q.y * k.y;
        }
        d += __shfl_xor_sync(0xffffffffu, d, 1);
        d += __shfl_xor_sync(0xffffffffu, d, 2);
        float ex = __expf(d);
        ssA += ex;
        const __half2* mh = reinterpret_cast<const __half2*>(&mraw);
        float2 m0 = __half22float2(mh[0]), m1 = __half22float2(mh[1]);
        float2 m2 = __half22float2(mh[2]), m3 = __half22float2(mh[3]);
        aA0 += ex * m0.x; aA1 += ex * m0.y; aA2 += ex * m1.x; aA3 += ex * m1.y;
        aA4 += ex * m2.x; aA5 += ex * m2.y; aA6 += ex * m3.x; aA7 += ex * m3.y;
    }
    float ssum = ssA + ssB;
    float inv = (ssum > 0.f) ? 1.f / ssum : 0.f;
    float4* o = reinterpret_cast<float4*>(g_aggr + (size_t)dst * DD + lane * 8);
    __stcs(o, make_float4((aA0 + aB0) * inv, (aA1 + aB1) * inv,
                          (aA2 + aB2) * inv, (aA3 + aB3) * inv));
    __stcs(o + 1, make_float4((aA4 + aB4) * inv, (aA5 + aB5) * inv,
                              (aA6 + aB6) * inv, (aA7 + aB7) * inv));
}

// ---------------- classifier + log_softmax ---------------------------------
__global__ __launch_bounds__(256) void k_out(const float* __restrict__ Wout,
                                             const float* __restrict__ bout,
                                             float* __restrict__ out) {
    __shared__ float Ws[DD * CC];
    __shared__ float Hs[16][DD];
    int tid = threadIdx.x;
    for (int i = tid; i < DD * CC; i += 256) Ws[i] = Wout[i];
    int nodeBase = blockIdx.x * 16;
    for (int i = tid; i < 16 * 64; i += 256) {
        int row = i >> 6, c4 = i & 63;
        int node = nodeBase + row;
        float4 v = (node < NN)
                       ? *reinterpret_cast<const float4*>(
                             g_hbuf + (size_t)node * DD + c4 * 4)
                       : make_float4(0.f, 0.f, 0.f, 0.f);
        *reinterpret_cast<float4*>(&Hs[row][c4 * 4]) = v;
    }
    __syncthreads();

    int node = nodeBase + (tid >> 4);
    int c = tid & 15;
    float acc = bout[c];
    const float* hrow = &Hs[tid >> 4][0];
#pragma unroll 8
    for (int k = 0; k < DD; k++) acc += hrow[k] * Ws[k * CC + c];

    float m = acc;
#pragma unroll
    for (int off = 8; off; off >>= 1)
        m = fmaxf(m, __shfl_xor_sync(0xffffffffu, m, off, 16));
    float ee = expf(acc - m);
    float s = ee;
#pragma unroll
    for (int off = 8; off; off >>= 1)
        s += __shfl_xor_sync(0xffffffffu, s, off, 16);
    if (node < NN) out[(size_t)node * CC + c] = acc - m - logf(s);
}

// ---------------- launcher --------------------------------------------------
extern "C" void kernel_launch(void* const* d_in, const int* in_sizes, int n_in,
                              void* d_out, int out_size) {
    const float* x = (const float*)d_in[0];
    const int* ei = (const int*)d_in[1];
    const int* nt = (const int*)d_in[2];
    const int* et = (const int*)d_in[3];
    const float* Wk = (const float*)d_in[4];
    const float* bk = (const float*)d_in[5];
    const float* Wq = (const float*)d_in[6];
    const float* bq = (const float*)d_in[7];
    const float* Wv = (const float*)d_in[8];
    const float* bv = (const float*)d_in[9];
    const float* Wa = (const float*)d_in[10];
    const float* ba = (const float*)d_in[11];
    const float* prior = (const float*)d_in[12];
    const float* rel_att = (const float*)d_in[13];
    const float* rel_msg = (const float*)d_in[14];
    const float* Wout = (const float*)d_in[15];
    const float* bout = (const float*)d_in[16];
    float* out = (float*)d_out;

    // fork: edge-sorting chain runs on side stream, overlapped with the
    // node bucketing + projection/transform GEMMs on the main stream.
    // g_deg starts zeroed (static init) and k_scanE re-zeroes it each call.
    cudaEventRecord(g_evFork, 0);
    cudaStreamWaitEvent(g_s2, g_evFork, 0);
    k_countE<<<(EE + 255) / 256, 256, 0, g_s2>>>(ei);
    k_scanE<<<1, 1024, 0, g_s2>>>();
    k_placeE<<<(EE + 255) / 256, 256, 0, g_s2>>>(ei, et);
    cudaEventRecord(g_evJoin, g_s2);

    // main stream: single-kernel node bucketing
    k_nodeprep<<<1, 1024>>>(nt);

    dim3 gKQV((NN + 127) / 128, DD / 64, 3 * TT);
    k_typed_kqv<<<gKQV, 256>>>(x, Wk, bk, Wq, bq, Wv, bv);

    dim3 gRel((NN + 127) / 128, HH, 2);
    k_rel_mma<<<gRel, 256>>>(rel_att, rel_msg, prior);

    // join: edge order must be ready before k_edge
    cudaStreamWaitEvent(0, g_evJoin, 0);
    k_edge<<<(NN * 32 + 255) / 256, 256>>>();

    dim3 gUpd((NN + 127) / 128, DD / 64, TT);
    k_typed_upd<<<gUpd, 256>>>(x, Wa, ba);

    k_out<<<(NN + 15) / 16, 256>>>(Wout, bout, out);
}

// round 15
// speedup vs baseline: 1.0429x; 1.0429x over previous
#include <cuda_runtime.h>
#include <cuda_fp16.h>
#include <math.h>
#include <stdint.h>

#define NN 20000
#define EE 320000
#define DD 256
#define HH 8
#define KD 32
#define TT 3
#define RR 5
#define CC 16

// ---------------- scratch (static device globals; no allocation) ----------
__device__ __half g_Kn[NN * DD];                 // fp16 keys
__device__ float  g_Qn[NN * DD];                 // fp32 queries
__device__ float  g_Vn[NN * DD];                 // fp32 values
__device__ __half g_Qt[(size_t)RR * NN * DD];    // prior/sqrtK * rel_att^T . Q
__device__ __half g_MtN[(size_t)RR * NN * DD];   // rel_msg transform of V
__device__ float  g_aggr[NN * DD];
__device__ float  g_hbuf[NN * DD];
__device__ int    g_order[NN];
__device__ int    g_cnt[TT];
__device__ int    g_cntTmp[TT];   // zero at load; re-zeroed by k_offsets
__device__ int    g_base[TT];
__device__ int    g_cur[TT];
__device__ int    g_deg[NN];      // zero at load; re-zeroed by k_scanE
__device__ int    g_start[NN + 1];
__device__ int    g_cur2[NN];
__device__ int    g_epack[EE];    // src | (r << 24), sorted by dst

// ---------------- side stream + events for graph fork/join ------------------
static cudaStream_t g_s2;
static cudaEvent_t  g_evFork, g_evJoin;
static const bool g_side_init = [] {
    cudaStreamCreateWithFlags(&g_s2, cudaStreamNonBlocking);
    cudaEventCreateWithFlags(&g_evFork, cudaEventDisableTiming);
    cudaEventCreateWithFlags(&g_evJoin, cudaEventDisableTiming);
    return true;
}();

// ---------------- helpers --------------------------------------------------
__device__ __forceinline__ void mma_f16(float* d, const uint32_t* a,
                                        const uint32_t* b) {
    asm volatile(
        "mma.sync.aligned.m16n8k16.row.col.f32.f16.f16.f32 "
        "{%0,%1,%2,%3}, {%4,%5,%6,%7}, {%8,%9}, {%0,%1,%2,%3};\n"
        : "+f"(d[0]), "+f"(d[1]), "+f"(d[2]), "+f"(d[3])
        : "r"(a[0]), "r"(a[1]), "r"(a[2]), "r"(a[3]), "r"(b[0]), "r"(b[1]));
}

__device__ __forceinline__ uint32_t h2u(const __half2& h) {
    return *reinterpret_cast<const uint32_t*>(&h);
}

// ---------------- node bucketing: 3 kernels (multi-block) --------------------
__global__ void k_countN(const int* __restrict__ nt) {
    int i = blockIdx.x * blockDim.x + threadIdx.x;
    if (i < NN) atomicAdd(&g_cntTmp[nt[i]], 1);
}

__global__ void k_offsets() {
    if (threadIdx.x == 0) {
        int s = 0;
        for (int t = 0; t < TT; t++) {
            int c = g_cntTmp[t];
            g_cntTmp[t] = 0;          // re-zero for next replay
            g_cnt[t] = c;
            g_base[t] = s;
            g_cur[t] = s;
            s += c;
        }
    }
}

__global__ void k_scatterN(const int* __restrict__ nt) {
    int i = blockIdx.x * blockDim.x + threadIdx.x;
    if (i < NN) {
        int t = nt[i];
        int p = atomicAdd(&g_cur[t], 1);
        g_order[p] = i;
    }
}

// ---------------- edge-side setup (side stream) ------------------------------
__global__ void k_countE(const int* __restrict__ ei) {
    int i = blockIdx.x * blockDim.x + threadIdx.x;
    if (i < EE) atomicAdd(&g_deg[ei[EE + i]], 1);
}

__global__ __launch_bounds__(1024) void k_scanE() {
    __shared__ int part[1024];
    const int tid = threadIdx.x;
    const int CH = (NN + 1023) / 1024;
    int base = tid * CH;
    int s = 0;
    for (int j = 0; j < CH; j++)
        if (base + j < NN) s += g_deg[base + j];
    part[tid] = s;
    __syncthreads();
    for (int off = 1; off < 1024; off <<= 1) {
        int v = (tid >= off) ? part[tid - off] : 0;
        __syncthreads();
        part[tid] += v;
        __syncthreads();
    }
    int run = (tid == 0) ? 0 : part[tid - 1];
    for (int j = 0; j < CH; j++) {
        if (base + j < NN) {
            int d = g_deg[base + j];
            g_deg[base + j] = 0;          // re-zero for the next replay
            g_start[base + j] = run;
            g_cur2[base + j] = run;
            run += d;
        }
    }
    if (tid == 1023) g_start[NN] = part[1023];
}

__global__ void k_placeE(const int* __restrict__ ei,
                         const int* __restrict__ et) {
    int i = blockIdx.x * blockDim.x + threadIdx.x;
    if (i < EE) {
        int dst = ei[EE + i];
        int pos = atomicAdd(&g_cur2[dst], 1);
        g_epack[pos] = ei[i] | (et[i] << 24);
    }
}

// ---------------- typed (gathered) linear via fp16 mma ---------------------
// Smem tiles are __half2 with k-pairs packed (As[kp][m], Bs[kp][n]); one
// 32-bit LDS per fragment register, conversion done once at staging.
// MODE 0 : Out = X @ W[t] + b[t]
// MODE 3 : Out = elu(g_aggr) @ W[t] + b[t] + x  (residual, float out)
template <int MODE, typename OutT>
__device__ __forceinline__ void typed_gemm_body(
    const float* __restrict__ X, const float* __restrict__ Xres,
    const float* __restrict__ W, const float* __restrict__ bvec,
    OutT* __restrict__ Out, int t, int m0, int n0) {
    const int cnt = g_cnt[t];
    if (m0 >= cnt) return;
    const int base = g_base[t];
    const int tid = threadIdx.x;
    const int lane = tid & 31, wid = tid >> 5;
    const int wm = wid & 3, wn = wid >> 2;
    const int grp = lane >> 2, tig = lane & 3;

    __shared__ __half2 As[16][136];   // [kp][m], row stride 136 (%32 == 8)
    __shared__ __half2 Bs[16][72];    // [kp][n], row stride 72  (%32 == 8)

    const int arow = tid >> 1;
    const int kpbase = (tid & 1) * 8;
    const int acol0 = (tid & 1) * 16;
    const int am = m0 + arow;
    const float* aptr = nullptr;
    if (am < cnt) aptr = X + (size_t)g_order[base + am] * DD + acol0;

    const int bkp = tid >> 4;          // 0..15
    const int bnq = (tid & 15) * 4;    // 0..60

    float acc[2][4][4];
#pragma unroll
    for (int i = 0; i < 2; i++)
#pragma unroll
        for (int j = 0; j < 4; j++)
#pragma unroll
            for (int k = 0; k < 4; k++) acc[i][j][k] = 0.f;

    for (int kk = 0; kk < DD; kk += 32) {
#pragma unroll
        for (int j = 0; j < 4; j++) {
            float4 v = make_float4(0.f, 0.f, 0.f, 0.f);
            if (aptr) v = *reinterpret_cast<const float4*>(aptr + kk + j * 4);
            if (MODE == 3) {
                v.x = v.x > 0.f ? v.x : expm1f(v.x);
                v.y = v.y > 0.f ? v.y : expm1f(v.y);
                v.z = v.z > 0.f ? v.z : expm1f(v.z);
                v.w = v.w > 0.f ? v.w : expm1f(v.w);
            }
            As[kpbase + j * 2 + 0][arow] = __floats2half2_rn(v.x, v.y);
            As[kpbase + j * 2 + 1][arow] = __floats2half2_rn(v.z, v.w);
        }
        {
            float4 v0 = *reinterpret_cast<const float4*>(
                W + (size_t)(kk + 2 * bkp) * DD + n0 + bnq);
            float4 v1 = *reinterpret_cast<const float4*>(
                W + (size_t)(kk + 2 * bkp + 1) * DD + n0 + bnq);
            Bs[bkp][bnq + 0] = __floats2half2_rn(v0.x, v1.x);
            Bs[bkp][bnq + 1] = __floats2half2_rn(v0.y, v1.y);
            Bs[bkp][bnq + 2] = __floats2half2_rn(v0.z, v1.z);
            Bs[bkp][bnq + 3] = __floats2half2_rn(v0.w, v1.w);
        }
        __syncthreads();
#pragma unroll
        for (int ks = 0; ks < 2; ks++) {
            const int kp0 = ks * 8 + tig;
            uint32_t a[2][4], b[4][2];
#pragma unroll
            for (int mt = 0; mt < 2; mt++) {
                int mb = wm * 32 + mt * 16 + grp;
                a[mt][0] = h2u(As[kp0][mb]);
                a[mt][1] = h2u(As[kp0][mb + 8]);
                a[mt][2] = h2u(As[kp0 + 4][mb]);
                a[mt][3] = h2u(As[kp0 + 4][mb + 8]);
            }
#pragma unroll
            for (int nt = 0; nt < 4; nt++) {
                int nb = wn * 32 + nt * 8 + grp;
                b[nt][0] = h2u(Bs[kp0][nb]);
                b[nt][1] = h2u(Bs[kp0 + 4][nb]);
            }
#pragma unroll
            for (int mt = 0; mt < 2; mt++)
#pragma unroll
                for (int nt = 0; nt < 4; nt++)
                    mma_f16(acc[mt][nt], a[mt], b[nt]);
        }
        __syncthreads();
    }

#pragma unroll
    for (int mt = 0; mt < 2; mt++) {
        int mr0 = m0 + wm * 32 + mt * 16 + grp;
        int mr1 = mr0 + 8;
        int node0 = (mr0 < cnt) ? g_order[base + mr0] : -1;
        int node1 = (mr1 < cnt) ? g_order[base + mr1] : -1;
#pragma unroll
        for (int nt = 0; nt < 4; nt++) {
            int col = n0 + wn * 32 + nt * 8 + tig * 2;
            float2 bi = *reinterpret_cast<const float2*>(bvec + col);
            if (node0 >= 0) {
                float o0 = acc[mt][nt][0] + bi.x;
                float o1 = acc[mt][nt][1] + bi.y;
                if (MODE == 3) {
                    float2 rr = *reinterpret_cast<const float2*>(
                        Xres + (size_t)node0 * DD + col);
                    o0 += rr.x; o1 += rr.y;
                }
                OutT* dst = Out + (size_t)node0 * DD + col;
                if (sizeof(OutT) == 2)
                    *reinterpret_cast<__half2*>(dst) = __floats2half2_rn(o0, o1);
                else
                    *reinterpret_cast<float2*>(dst) = make_float2(o0, o1);
            }
            if (node1 >= 0) {
                float o0 = acc[mt][nt][2] + bi.x;
                float o1 = acc[mt][nt][3] + bi.y;
                if (MODE == 3) {
                    float2 rr = *reinterpret_cast<const float2*>(
                        Xres + (size_t)node1 * DD + col);
                    o0 += rr.x; o1 += rr.y;
                }
                OutT* dst = Out + (size_t)node1 * DD + col;
                if (sizeof(OutT) == 2)
                    *reinterpret_cast<__half2*>(dst) = __floats2half2_rn(o0, o1);
                else
                    *reinterpret_cast<float2*>(dst) = make_float2(o0, o1);
            }
        }
    }
}

// fused K/Q/V projection: grid.z = 3*TT (which = z/TT, t = z%TT)
__global__ __launch_bounds__(256) void k_typed_kqv(
    const float* __restrict__ x,
    const float* __restrict__ Wk, const float* __restrict__ bk,
    const float* __restrict__ Wq, const float* __restrict__ bq,
    const float* __restrict__ Wv, const float* __restrict__ bv) {
    const int z = blockIdx.z;
    const int which = z / TT;
    const int t = z % TT;
    if (which == 0)
        typed_gemm_body<0, __half>(x, nullptr, Wk + (size_t)t * DD * DD,
                                   bk + t * DD, g_Kn, t, blockIdx.x * 128,
                                   blockIdx.y * 64);
    else if (which == 1)
        typed_gemm_body<0, float>(x, nullptr, Wq + (size_t)t * DD * DD,
                                  bq + t * DD, g_Qn, t, blockIdx.x * 128,
                                  blockIdx.y * 64);
    else
        typed_gemm_body<0, float>(x, nullptr, Wv + (size_t)t * DD * DD,
                                  bv + t * DD, g_Vn, t, blockIdx.x * 128,
                                  blockIdx.y * 64);
}

// update: g_hbuf = elu(g_aggr) @ Wa[t] + ba[t] + x
__global__ __launch_bounds__(256) void k_typed_upd(
    const float* __restrict__ x, const float* __restrict__ Wa,
    const float* __restrict__ ba) {
    const int t = blockIdx.z;
    typed_gemm_body<3, float>(g_aggr, x, Wa + (size_t)t * DD * DD, ba + t * DD,
                              g_hbuf, t, blockIdx.x * 128, blockIdx.y * 64);
}

// ---------------- Qt / MtN transforms via fp16 mma, fp16 output -------------
// z=0: g_Qt [r,n,h,k] = prh * sum_l rel_att[r,h,k,l] * Qn[n,h,l]  (transposed B)
// z=1: g_MtN[r,n,h,l] = sum_k Vn[n,h,k] * rel_msg[r,h,k,l]        (natural B)
__global__ __launch_bounds__(256) void k_rel_mma(
    const float* __restrict__ rel_att, const float* __restrict__ rel_msg,
    const float* __restrict__ prior) {
    const int h = blockIdx.y;
    const int which = blockIdx.z;
    const float* In = which ? g_Vn : g_Qn;
    const float* Rel = which ? rel_msg : rel_att;
    __half* Out = which ? g_MtN : g_Qt;
    const int nbase = blockIdx.x * 128;
    const int tid = threadIdx.x;
    const int lane = tid & 31, wid = tid >> 5;
    const int wm = wid & 3, wn = wid >> 2;
    const int grp = lane >> 2, tig = lane & 3;

    __shared__ __half2 As[16][136];     // [kp][m]
    __shared__ __half2 Bs[5][16][40];   // [r][kp][n], row stride 40 (%32 == 8)

    {
        int arow = tid >> 1;
        int kpbase = (tid & 1) * 8;
        int acol0 = (tid & 1) * 16;
        int node = nbase + arow;
        const float* ap = (node < NN)
                              ? In + (size_t)node * DD + h * KD + acol0
                              : nullptr;
#pragma unroll
        for (int j = 0; j < 4; j++) {
            float4 v = ap ? *reinterpret_cast<const float4*>(ap + j * 4)
                          : make_float4(0.f, 0.f, 0.f, 0.f);
            As[kpbase + j * 2 + 0][arow] = __floats2half2_rn(v.x, v.y);
            As[kpbase + j * 2 + 1][arow] = __floats2half2_rn(v.z, v.w);
        }
        if (which == 0) {
#pragma unroll
            for (int j = 0; j < 5; j++) {
                int f = tid + j * 256;
                int r = f >> 8;
                int rem = f & 255;
                int k = rem >> 3, lq = (rem & 7) * 4;
                float4 v = *reinterpret_cast<const float4*>(
                    Rel + (size_t)(r * HH + h) * (KD * KD) + k * KD + lq);
                Bs[r][lq / 2 + 0][k] = __floats2half2_rn(v.x, v.y);
                Bs[r][lq / 2 + 1][k] = __floats2half2_rn(v.z, v.w);
            }
        } else {
            for (int f = tid; f < 640; f += 256) {
                int r = f >> 7;
                int rem = f & 127;
                int kp = rem >> 3, lq = (rem & 7) * 4;
                const float* rb =
                    Rel + (size_t)(r * HH + h) * (KD * KD) + (2 * kp) * KD + lq;
                float4 v0 = *reinterpret_cast<const float4*>(rb);
                float4 v1 = *reinterpret_cast<const float4*>(rb + KD);
                Bs[r][kp][lq + 0] = __floats2half2_rn(v0.x, v1.x);
                Bs[r][kp][lq + 1] = __floats2half2_rn(v0.y, v1.y);
                Bs[r][kp][lq + 2] = __floats2half2_rn(v0.z, v1.z);
                Bs[r][kp][lq + 3] = __floats2half2_rn(v0.w, v1.w);
            }
        }
    }
    __syncthreads();

    uint32_t a[2][2][4];
#pragma unroll
    for (int ks = 0; ks < 2; ks++) {
        int kp0 = ks * 8 + tig;
#pragma unroll
        for (int mt = 0; mt < 2; mt++) {
            int mb = wm * 32 + mt * 16 + grp;
            a[ks][mt][0] = h2u(As[kp0][mb]);
            a[ks][mt][1] = h2u(As[kp0][mb + 8]);
            a[ks][mt][2] = h2u(As[kp0 + 4][mb]);
            a[ks][mt][3] = h2u(As[kp0 + 4][mb + 8]);
        }
    }

    for (int r = 0; r < RR; r++) {
        const float scale =
            which ? 1.f : prior[r * HH + h] * 0.17677669529663688f;
        float acc[2][2][4];
#pragma unroll
        for (int i = 0; i < 2; i++)
#pragma unroll
            for (int j = 0; j < 2; j++)
#pragma unroll
                for (int k = 0; k < 4; k++) acc[i][j][k] = 0.f;
#pragma unroll
        for (int ks = 0; ks < 2; ks++) {
            int kp0 = ks * 8 + tig;
            uint32_t b[2][2];
#pragma unroll
            for (int nt = 0; nt < 2; nt++) {
                int nb = wn * 16 + nt * 8 + grp;
                b[nt][0] = h2u(Bs[r][kp0][nb]);
                b[nt][1] = h2u(Bs[r][kp0 + 4][nb]);
            }
#pragma unroll
            for (int mt = 0; mt < 2; mt++)
#pragma unroll
                for (int nt = 0; nt < 2; nt++)
                    mma_f16(acc[mt][nt], a[ks][mt], b[nt]);
        }
        __half* Or = Out + (size_t)r * NN * DD;
#pragma unroll
        for (int mt = 0; mt < 2; mt++) {
            int nr0 = nbase + wm * 32 + mt * 16 + grp;
            int nr1 = nr0 + 8;
#pragma unroll
            for (int nt = 0; nt < 2; nt++) {
                int col = h * KD + wn * 16 + nt * 8 + tig * 2;
                if (nr0 < NN)
                    *reinterpret_cast<__half2*>(Or + (size_t)nr0 * DD + col) =
                        __floats2half2_rn(acc[mt][nt][0] * scale,
                                          acc[mt][nt][1] * scale);
                if (nr1 < NN)
                    *reinterpret_cast<__half2*>(Or + (size_t)nr1 * DD + col) =
                        __floats2half2_rn(acc[mt][nt][2] * scale,
                                          acc[mt][nt][3] * scale);
            }
        }
    }
}

// ---------------- fused edge phase: one warp per destination ---------------
__global__ __launch_bounds__(256) void k_edge() {
    __shared__ __half sQt[8][RR][256];
    int gw = (blockIdx.x * 256 + threadIdx.x) >> 5;
    if (gw >= NN) return;
    const int w = (threadIdx.x >> 5) & 7;
    const int lane = threadIdx.x & 31;
    const int dst = gw;
    const int s0 = g_start[dst], s1 = g_start[dst + 1];

#pragma unroll
    for (int r = 0; r < RR; r++) {
        float4 q = __ldcs(reinterpret_cast<const float4*>(
            g_Qt + ((size_t)r * NN + dst) * DD + lane * 8));
        *reinterpret_cast<float4*>(&sQt[w][r][lane * 8]) = q;
    }
    // no sync: each lane reads only its own slot

    float ssA = 0.f, ssB = 0.f;
    float aA0 = 0.f, aA1 = 0.f, aA2 = 0.f, aA3 = 0.f;
    float aA4 = 0.f, aA5 = 0.f, aA6 = 0.f, aA7 = 0.f;
    float aB0 = 0.f, aB1 = 0.f, aB2 = 0.f, aB3 = 0.f;
    float aB4 = 0.f, aB5 = 0.f, aB6 = 0.f, aB7 = 0.f;

    int i = s0;
    for (; i + 2 <= s1; i += 2) {
        int pk0 = __ldcs(g_epack + i);
        int pk1 = __ldcs(g_epack + i + 1);
        int r0 = ((unsigned)pk0) >> 24, r1 = ((unsigned)pk1) >> 24;
        size_t ko0 = (size_t)(pk0 & 0xFFFFFF) * DD + lane * 8;
        size_t ko1 = (size_t)(pk1 & 0xFFFFFF) * DD + lane * 8;
        float4 kraw0 = *reinterpret_cast<const float4*>(g_Kn + ko0);
        float4 kraw1 = *reinterpret_cast<const float4*>(g_Kn + ko1);
        float4 mraw0 =
            *reinterpret_cast<const float4*>(g_MtN + (size_t)r0 * NN * DD + ko0);
        float4 mraw1 =
            *reinterpret_cast<const float4*>(g_MtN + (size_t)r1 * NN * DD + ko1);
        float4 qraw0 = *reinterpret_cast<const float4*>(&sQt[w][r0][lane * 8]);
        float4 qraw1 = *reinterpret_cast<const float4*>(&sQt[w][r1][lane * 8]);

        const __half2* qh0 = reinterpret_cast<const __half2*>(&qraw0);
        const __half2* qh1 = reinterpret_cast<const __half2*>(&qraw1);
        const __half2* kh0 = reinterpret_cast<const __half2*>(&kraw0);
        const __half2* kh1 = reinterpret_cast<const __half2*>(&kraw1);
        float d0 = 0.f, d1 = 0.f;
#pragma unroll
        for (int j = 0; j < 4; j++) {
            float2 q0 = __half22float2(qh0[j]);
            float2 k0 = __half22float2(kh0[j]);
            float2 q1 = __half22float2(qh1[j]);
            float2 k1 = __half22float2(kh1[j]);
            d0 += q0.x * k0.x + q0.y * k0.y;
            d1 += q1.x * k1.x + q1.y * k1.y;
        }
        d0 += __shfl_xor_sync(0xffffffffu, d0, 1);
        d1 += __shfl_xor_sync(0xffffffffu, d1, 1);
        d0 += __shfl_xor_sync(0xffffffffu, d0, 2);
        d1 += __shfl_xor_sync(0xffffffffu, d1, 2);
        float ex0 = __expf(d0);
        float ex1 = __expf(d1);
        ssA += ex0;
        ssB += ex1;
        const __half2* mh0 = reinterpret_cast<const __half2*>(&mraw0);
        const __half2* mh1 = reinterpret_cast<const __half2*>(&mraw1);
        float2 m00 = __half22float2(mh0[0]), m01 = __half22float2(mh0[1]);
        float2 m02 = __half22float2(mh0[2]), m03 = __half22float2(mh0[3]);
        float2 m10 = __half22float2(mh1[0]), m11 = __half22float2(mh1[1]);
        float2 m12 = __half22float2(mh1[2]), m13 = __half22float2(mh1[3]);
        aA0 += ex0 * m00.x; aA1 += ex0 * m00.y;
        aA2 += ex0 * m01.x; aA3 += ex0 * m01.y;
        aA4 += ex0 * m02.x; aA5 += ex0 * m02.y;
        aA6 += ex0 * m03.x; aA7 += ex0 * m03.y;
        aB0 += ex1 * m10.x; aB1 += ex1 * m10.y;
        aB2 += ex1 * m11.x; aB3 += ex1 * m11.y;
        aB4 += ex1 * m12.x; aB5 += ex1 * m12.y;
        aB6 += ex1 * m13.x; aB7 += ex1 * m13.y;
    }
    if (i < s1) {
        int pk = __ldcs(g_epack + i);
        int r = ((unsigned)pk) >> 24;
        size_t ko = (size_t)(pk & 0xFFFFFF) * DD + lane * 8;
        float4 kraw = *reinterpret_cast<const float4*>(g_Kn + ko);
        float4 mraw =
            *reinterpret_cast<const float4*>(g_MtN + (size_t)r * NN * DD + ko);
        float4 qraw = *reinterpret_cast<const float4*>(&sQt[w][r][lane * 8]);
        const __half2* qh = reinterpret_cast<const __half2*>(&qraw);
        const __half2* kh = reinterpret_cast<const __half2*>(&kraw);
        float d = 0.f;
#pragma unroll
        for (int j = 0; j < 4; j++) {
            float2 q = __half22float2(qh[j]);
            float2 k = __half22float2(kh[j]);
            d += q.x * k.x + q.y * k.y;
        }
        d += __shfl_xor_sync(0xffffffffu, d, 1);
        d += __shfl_xor_sync(0xffffffffu, d, 2);
        float ex = __expf(d);
        ssA += ex;
        const __half2* mh = reinterpret_cast<const __half2*>(&mraw);
        float2 m0 = __half22float2(mh[0]), m1 = __half22float2(mh[1]);
        float2 m2 = __half22float2(mh[2]), m3 = __half22float2(mh[3]);
        aA0 += ex * m0.x; aA1 += ex * m0.y; aA2 += ex * m1.x; aA3 += ex * m1.y;
        aA4 += ex * m2.x; aA5 += ex * m2.y; aA6 += ex * m3.x; aA7 += ex * m3.y;
    }
    float ssum = ssA + ssB;
    float inv = (ssum > 0.f) ? 1.f / ssum : 0.f;
    float4* o = reinterpret_cast<float4*>(g_aggr + (size_t)dst * DD + lane * 8);
    __stcs(o, make_float4((aA0 + aB0) * inv, (aA1 + aB1) * inv,
                          (aA2 + aB2) * inv, (aA3 + aB3) * inv));
    __stcs(o + 1, make_float4((aA4 + aB4) * inv, (aA5 + aB5) * inv,
                              (aA6 + aB6) * inv, (aA7 + aB7) * inv));
}

// ---------------- classifier + log_softmax ---------------------------------
__global__ __launch_bounds__(256) void k_out(const float* __restrict__ Wout,
                                             const float* __restrict__ bout,
                                             float* __restrict__ out) {
    __shared__ float Ws[DD * CC];
    __shared__ float Hs[16][DD];
    int tid = threadIdx.x;
    for (int i = tid; i < DD * CC; i += 256) Ws[i] = Wout[i];
    int nodeBase = blockIdx.x * 16;
    for (int i = tid; i < 16 * 64; i += 256) {
        int row = i >> 6, c4 = i & 63;
        int node = nodeBase + row;
        float4 v = (node < NN)
                       ? *reinterpret_cast<const float4*>(
                             g_hbuf + (size_t)node * DD + c4 * 4)
                       : make_float4(0.f, 0.f, 0.f, 0.f);
        *reinterpret_cast<float4*>(&Hs[row][c4 * 4]) = v;
    }
    __syncthreads();

    int node = nodeBase + (tid >> 4);
    int c = tid & 15;
    float acc = bout[c];
    const float* hrow = &Hs[tid >> 4][0];
#pragma unroll 8
    for (int k = 0; k < DD; k++) acc += hrow[k] * Ws[k * CC + c];

    float m = acc;
#pragma unroll
    for (int off = 8; off; off >>= 1)
        m = fmaxf(m, __shfl_xor_sync(0xffffffffu, m, off, 16));
    float ee = expf(acc - m);
    float s = ee;
#pragma unroll
    for (int off = 8; off; off >>= 1)
        s += __shfl_xor_sync(0xffffffffu, s, off, 16);
    if (node < NN) out[(size_t)node * CC + c] = acc - m - logf(s);
}

// ---------------- launcher --------------------------------------------------
extern "C" void kernel_launch(void* const* d_in, const int* in_sizes, int n_in,
                              void* d_out, int out_size) {
    const float* x = (const float*)d_in[0];
    const int* ei = (const int*)d_in[1];
    const int* nt = (const int*)d_in[2];
    const int* et = (const int*)d_in[3];
    const float* Wk = (const float*)d_in[4];
    const float* bk = (const float*)d_in[5];
    const float* Wq = (const float*)d_in[6];
    const float* bq = (const float*)d_in[7];
    const float* Wv = (const float*)d_in[8];
    const float* bv = (const float*)d_in[9];
    const float* Wa = (const float*)d_in[10];
    const float* ba = (const float*)d_in[11];
    const float* prior = (const float*)d_in[12];
    const float* rel_att = (const float*)d_in[13];
    const float* rel_msg = (const float*)d_in[14];
    const float* Wout = (const float*)d_in[15];
    const float* bout = (const float*)d_in[16];
    float* out = (float*)d_out;

    // fork: edge-sorting chain runs on side stream, overlapped with the
    // node bucketing + projection/transform GEMMs on the main stream.
    // g_deg starts zeroed (static init) and k_scanE re-zeroes it each call.
    cudaEventRecord(g_evFork, 0);
    cudaStreamWaitEvent(g_s2, g_evFork, 0);
    k_countE<<<(EE + 255) / 256, 256, 0, g_s2>>>(ei);
    k_scanE<<<1, 1024, 0, g_s2>>>();
    k_placeE<<<(EE + 255) / 256, 256, 0, g_s2>>>(ei, et);
    cudaEventRecord(g_evJoin, g_s2);

    // main stream: multi-block node bucketing (g_cntTmp re-zeroed by k_offsets)
    k_countN<<<(NN + 255) / 256, 256>>>(nt);
    k_offsets<<<1, 32>>>();
    k_scatterN<<<(NN + 255) / 256, 256>>>(nt);

    dim3 gKQV((NN + 127) / 128, DD / 64, 3 * TT);
    k_typed_kqv<<<gKQV, 256>>>(x, Wk, bk, Wq, bq, Wv, bv);

    dim3 gRel((NN + 127) / 128, HH, 2);
    k_rel_mma<<<gRel, 256>>>(rel_att, rel_msg, prior);

    // join: edge order must be ready before k_edge
    cudaStreamWaitEvent(0, g_evJoin, 0);
    k_edge<<<(NN * 32 + 255) / 256, 256>>>();

    dim3 gUpd((NN + 127) / 128, DD / 64, TT);
    k_typed_upd<<<gUpd, 256>>>(x, Wa, ba);

    k_out<<<(NN + 15) / 16, 256>>>(Wout, bout, out);
}

// round 16
// speedup vs baseline: 1.0711x; 1.0270x over previous
#include <cuda_runtime.h>
#include <cuda_fp16.h>
#include <math.h>
#include <stdint.h>

#define NN 20000
#define EE 320000
#define DD 256
#define HH 8
#define KD 32
#define TT 3
#define RR 5
#define CC 16

// ---------------- scratch (static device globals; no allocation) ----------
__device__ __half g_Kn[NN * DD];                 // fp16 keys
__device__ float  g_Qn[NN * DD];                 // fp32 queries
__device__ float  g_Vn[NN * DD];                 // fp32 values
__device__ __half g_Qt[(size_t)RR * NN * DD];    // prior/sqrtK * rel_att^T . Q
__device__ __half g_MtN[(size_t)RR * NN * DD];   // rel_msg transform of V
__device__ float  g_aggr[NN * DD];
__device__ float  g_hbuf[NN * DD];
__device__ int    g_order[NN];
__device__ int    g_cnt[TT];
__device__ int    g_cntTmp[TT];   // zero at load; re-zeroed by k_offsets
__device__ int    g_base[TT];
__device__ int    g_cur[TT];
__device__ int    g_deg[NN];      // zero at load; re-zeroed by k_scanE
__device__ int    g_start[NN + 1];
__device__ int    g_cur2[NN];
__device__ int    g_epack[EE];    // src | (r << 24), sorted by dst

// ---------------- side stream + events for graph fork/join ------------------
static cudaStream_t g_s2;
static cudaEvent_t  g_evFork, g_evJoin;
static const bool g_side_init = [] {
    cudaStreamCreateWithFlags(&g_s2, cudaStreamNonBlocking);
    cudaEventCreateWithFlags(&g_evFork, cudaEventDisableTiming);
    cudaEventCreateWithFlags(&g_evJoin, cudaEventDisableTiming);
    return true;
}();

// ---------------- helpers --------------------------------------------------
__device__ __forceinline__ void mma_f16(float* d, const uint32_t* a,
                                        const uint32_t* b) {
    asm volatile(
        "mma.sync.aligned.m16n8k16.row.col.f32.f16.f16.f32 "
        "{%0,%1,%2,%3}, {%4,%5,%6,%7}, {%8,%9}, {%0,%1,%2,%3};\n"
        : "+f"(d[0]), "+f"(d[1]), "+f"(d[2]), "+f"(d[3])
        : "r"(a[0]), "r"(a[1]), "r"(a[2]), "r"(a[3]), "r"(b[0]), "r"(b[1]));
}

__device__ __forceinline__ uint32_t h2u(const __half2& h) {
    return *reinterpret_cast<const uint32_t*>(&h);
}

// ---------------- node bucketing: 3 kernels, aggregated atomics -------------
__global__ __launch_bounds__(512) void k_countN(const int* __restrict__ nt) {
    __shared__ int c[TT];
    if (threadIdx.x < TT) c[threadIdx.x] = 0;
    __syncthreads();
    int i = blockIdx.x * 512 + threadIdx.x;
    if (i < NN) atomicAdd(&c[nt[i]], 1);
    __syncthreads();
    if (threadIdx.x < TT && c[threadIdx.x])
        atomicAdd(&g_cntTmp[threadIdx.x], c[threadIdx.x]);
}

__global__ void k_offsets() {
    if (threadIdx.x == 0) {
        int s = 0;
        for (int t = 0; t < TT; t++) {
            int c = g_cntTmp[t];
            g_cntTmp[t] = 0;          // re-zero for next replay
            g_cnt[t] = c;
            g_base[t] = s;
            g_cur[t] = s;
            s += c;
        }
    }
}

__global__ __launch_bounds__(512) void k_scatterN(const int* __restrict__ nt) {
    int i = blockIdx.x * 512 + threadIdx.x;
    const int lane = threadIdx.x & 31;
    int t = (i < NN) ? nt[i] : -1;
#pragma unroll
    for (int tt = 0; tt < TT; tt++) {
        unsigned m = __ballot_sync(0xffffffffu, t == tt);
        if (t == tt) {
            int leader = __ffs(m) - 1;
            int posbase = 0;
            if (lane == leader) posbase = atomicAdd(&g_cur[tt], __popc(m));
            posbase = __shfl_sync(m, posbase, leader);
            g_order[posbase + __popc(m & ((1u << lane) - 1))] = i;
        }
    }
}

// ---------------- edge-side setup (side stream) ------------------------------
__global__ void k_countE(const int* __restrict__ ei) {
    int i = blockIdx.x * blockDim.x + threadIdx.x;
    if (i < EE) atomicAdd(&g_deg[ei[EE + i]], 1);
}

__global__ __launch_bounds__(1024) void k_scanE() {
    __shared__ int part[1024];
    const int tid = threadIdx.x;
    const int CH = (NN + 1023) / 1024;
    int base = tid * CH;
    int s = 0;
    for (int j = 0; j < CH; j++)
        if (base + j < NN) s += g_deg[base + j];
    part[tid] = s;
    __syncthreads();
    for (int off = 1; off < 1024; off <<= 1) {
        int v = (tid >= off) ? part[tid - off] : 0;
        __syncthreads();
        part[tid] += v;
        __syncthreads();
    }
    int run = (tid == 0) ? 0 : part[tid - 1];
    for (int j = 0; j < CH; j++) {
        if (base + j < NN) {
            int d = g_deg[base + j];
            g_deg[base + j] = 0;          // re-zero for the next replay
            g_start[base + j] = run;
            g_cur2[base + j] = run;
            run += d;
        }
    }
    if (tid == 1023) g_start[NN] = part[1023];
}

__global__ void k_placeE(const int* __restrict__ ei,
                         const int* __restrict__ et) {
    int i = blockIdx.x * blockDim.x + threadIdx.x;
    if (i < EE) {
        int dst = ei[EE + i];
        int pos = atomicAdd(&g_cur2[dst], 1);
        g_epack[pos] = ei[i] | (et[i] << 24);
    }
}

// ---------------- typed (gathered) linear via fp16 mma ---------------------
// Smem tiles are __half2 with k-pairs packed (As[kp][m], Bs[kp][n]); one
// 32-bit LDS per fragment register, conversion done once at staging.
// MODE 0 : Out = X @ W[t] + b[t]
// MODE 3 : Out = elu(g_aggr) @ W[t] + b[t] + x  (residual, float out)
template <int MODE, typename OutT>
__device__ __forceinline__ void typed_gemm_body(
    const float* __restrict__ X, const float* __restrict__ Xres,
    const float* __restrict__ W, const float* __restrict__ bvec,
    OutT* __restrict__ Out, int t, int m0, int n0) {
    const int cnt = g_cnt[t];
    if (m0 >= cnt) return;
    const int base = g_base[t];
    const int tid = threadIdx.x;
    const int lane = tid & 31, wid = tid >> 5;
    const int wm = wid & 3, wn = wid >> 2;
    const int grp = lane >> 2, tig = lane & 3;

    __shared__ __half2 As[16][136];   // [kp][m], row stride 136 (%32 == 8)
    __shared__ __half2 Bs[16][72];    // [kp][n], row stride 72  (%32 == 8)

    const int arow = tid >> 1;
    const int kpbase = (tid & 1) * 8;
    const int acol0 = (tid & 1) * 16;
    const int am = m0 + arow;
    const float* aptr = nullptr;
    if (am < cnt) aptr = X + (size_t)g_order[base + am] * DD + acol0;

    const int bkp = tid >> 4;          // 0..15
    const int bnq = (tid & 15) * 4;    // 0..60

    float acc[2][4][4];
#pragma unroll
    for (int i = 0; i < 2; i++)
#pragma unroll
        for (int j = 0; j < 4; j++)
#pragma unroll
            for (int k = 0; k < 4; k++) acc[i][j][k] = 0.f;

    for (int kk = 0; kk < DD; kk += 32) {
#pragma unroll
        for (int j = 0; j < 4; j++) {
            float4 v = make_float4(0.f, 0.f, 0.f, 0.f);
            if (aptr) v = *reinterpret_cast<const float4*>(aptr + kk + j * 4);
            if (MODE == 3) {
                v.x = v.x > 0.f ? v.x : expm1f(v.x);
                v.y = v.y > 0.f ? v.y : expm1f(v.y);
                v.z = v.z > 0.f ? v.z : expm1f(v.z);
                v.w = v.w > 0.f ? v.w : expm1f(v.w);
            }
            As[kpbase + j * 2 + 0][arow] = __floats2half2_rn(v.x, v.y);
            As[kpbase + j * 2 + 1][arow] = __floats2half2_rn(v.z, v.w);
        }
        {
            float4 v0 = *reinterpret_cast<const float4*>(
                W + (size_t)(kk + 2 * bkp) * DD + n0 + bnq);
            float4 v1 = *reinterpret_cast<const float4*>(
                W + (size_t)(kk + 2 * bkp + 1) * DD + n0 + bnq);
            Bs[bkp][bnq + 0] = __floats2half2_rn(v0.x, v1.x);
            Bs[bkp][bnq + 1] = __floats2half2_rn(v0.y, v1.y);
            Bs[bkp][bnq + 2] = __floats2half2_rn(v0.z, v1.z);
            Bs[bkp][bnq + 3] = __floats2half2_rn(v0.w, v1.w);
        }
        __syncthreads();
#pragma unroll
        for (int ks = 0; ks < 2; ks++) {
            const int kp0 = ks * 8 + tig;
            uint32_t a[2][4], b[4][2];
#pragma unroll
            for (int mt = 0; mt < 2; mt++) {
                int mb = wm * 32 + mt * 16 + grp;
                a[mt][0] = h2u(As[kp0][mb]);
                a[mt][1] = h2u(As[kp0][mb + 8]);
                a[mt][2] = h2u(As[kp0 + 4][mb]);
                a[mt][3] = h2u(As[kp0 + 4][mb + 8]);
            }
#pragma unroll
            for (int nt = 0; nt < 4; nt++) {
                int nb = wn * 32 + nt * 8 + grp;
                b[nt][0] = h2u(Bs[kp0][nb]);
                b[nt][1] = h2u(Bs[kp0 + 4][nb]);
            }
#pragma unroll
            for (int mt = 0; mt < 2; mt++)
#pragma unroll
                for (int nt = 0; nt < 4; nt++)
                    mma_f16(acc[mt][nt], a[mt], b[nt]);
        }
        __syncthreads();
    }

#pragma unroll
    for (int mt = 0; mt < 2; mt++) {
        int mr0 = m0 + wm * 32 + mt * 16 + grp;
        int mr1 = mr0 + 8;
        int node0 = (mr0 < cnt) ? g_order[base + mr0] : -1;
        int node1 = (mr1 < cnt) ? g_order[base + mr1] : -1;
#pragma unroll
        for (int nt = 0; nt < 4; nt++) {
            int col = n0 + wn * 32 + nt * 8 + tig * 2;
            float2 bi = *reinterpret_cast<const float2*>(bvec + col);
            if (node0 >= 0) {
                float o0 = acc[mt][nt][0] + bi.x;
                float o1 = acc[mt][nt][1] + bi.y;
                if (MODE == 3) {
                    float2 rr = *reinterpret_cast<const float2*>(
                        Xres + (size_t)node0 * DD + col);
                    o0 += rr.x; o1 += rr.y;
                }
                OutT* dst = Out + (size_t)node0 * DD + col;
                if (sizeof(OutT) == 2)
                    *reinterpret_cast<__half2*>(dst) = __floats2half2_rn(o0, o1);
                else
                    *reinterpret_cast<float2*>(dst) = make_float2(o0, o1);
            }
            if (node1 >= 0) {
                float o0 = acc[mt][nt][2] + bi.x;
                float o1 = acc[mt][nt][3] + bi.y;
                if (MODE == 3) {
                    float2 rr = *reinterpret_cast<const float2*>(
                        Xres + (size_t)node1 * DD + col);
                    o0 += rr.x; o1 += rr.y;
                }
                OutT* dst = Out + (size_t)node1 * DD + col;
                if (sizeof(OutT) == 2)
                    *reinterpret_cast<__half2*>(dst) = __floats2half2_rn(o0, o1);
                else
                    *reinterpret_cast<float2*>(dst) = make_float2(o0, o1);
            }
        }
    }
}

// fused K/Q/V projection: grid.z = 3*TT (which = z/TT, t = z%TT)
__global__ __launch_bounds__(256) void k_typed_kqv(
    const float* __restrict__ x,
    const float* __restrict__ Wk, const float* __restrict__ bk,
    const float* __restrict__ Wq, const float* __restrict__ bq,
    const float* __restrict__ Wv, const float* __restrict__ bv) {
    const int z = blockIdx.z;
    const int which = z / TT;
    const int t = z % TT;
    if (which == 0)
        typed_gemm_body<0, __half>(x, nullptr, Wk + (size_t)t * DD * DD,
                                   bk + t * DD, g_Kn, t, blockIdx.x * 128,
                                   blockIdx.y * 64);
    else if (which == 1)
        typed_gemm_body<0, float>(x, nullptr, Wq + (size_t)t * DD * DD,
                                  bq + t * DD, g_Qn, t, blockIdx.x * 128,
                                  blockIdx.y * 64);
    else
        typed_gemm_body<0, float>(x, nullptr, Wv + (size_t)t * DD * DD,
                                  bv + t * DD, g_Vn, t, blockIdx.x * 128,
                                  blockIdx.y * 64);
}

// update: g_hbuf = elu(g_aggr) @ Wa[t] + ba[t] + x
__global__ __launch_bounds__(256) void k_typed_upd(
    const float* __restrict__ x, const float* __restrict__ Wa,
    const float* __restrict__ ba) {
    const int t = blockIdx.z;
    typed_gemm_body<3, float>(g_aggr, x, Wa + (size_t)t * DD * DD, ba + t * DD,
                              g_hbuf, t, blockIdx.x * 128, blockIdx.y * 64);
}

// ---------------- Qt / MtN transforms via fp16 mma, fp16 output -------------
// z=0: g_Qt [r,n,h,k] = prh * sum_l rel_att[r,h,k,l] * Qn[n,h,l]  (transposed B)
// z=1: g_MtN[r,n,h,l] = sum_k Vn[n,h,k] * rel_msg[r,h,k,l]        (natural B)
__global__ __launch_bounds__(256) void k_rel_mma(
    const float* __restrict__ rel_att, const float* __restrict__ rel_msg,
    const float* __restrict__ prior) {
    const int h = blockIdx.y;
    const int which = blockIdx.z;
    const float* In = which ? g_Vn : g_Qn;
    const float* Rel = which ? rel_msg : rel_att;
    __half* Out = which ? g_MtN : g_Qt;
    const int nbase = blockIdx.x * 128;
    const int tid = threadIdx.x;
    const int lane = tid & 31, wid = tid >> 5;
    const int wm = wid & 3, wn = wid >> 2;
    const int grp = lane >> 2, tig = lane & 3;

    __shared__ __half2 As[16][136];     // [kp][m]
    __shared__ __half2 Bs[5][16][40];   // [r][kp][n], row stride 40 (%32 == 8)

    {
        int arow = tid >> 1;
        int kpbase = (tid & 1) * 8;
        int acol0 = (tid & 1) * 16;
        int node = nbase + arow;
        const float* ap = (node < NN)
                              ? In + (size_t)node * DD + h * KD + acol0
                              : nullptr;
#pragma unroll
        for (int j = 0; j < 4; j++) {
            float4 v = ap ? *reinterpret_cast<const float4*>(ap + j * 4)
                          : make_float4(0.f, 0.f, 0.f, 0.f);
            As[kpbase + j * 2 + 0][arow] = __floats2half2_rn(v.x, v.y);
            As[kpbase + j * 2 + 1][arow] = __floats2half2_rn(v.z, v.w);
        }
        if (which == 0) {
#pragma unroll
            for (int j = 0; j < 5; j++) {
                int f = tid + j * 256;
                int r = f >> 8;
                int rem = f & 255;
                int k = rem >> 3, lq = (rem & 7) * 4;
                float4 v = *reinterpret_cast<const float4*>(
                    Rel + (size_t)(r * HH + h) * (KD * KD) + k * KD + lq);
                Bs[r][lq / 2 + 0][k] = __floats2half2_rn(v.x, v.y);
                Bs[r][lq / 2 + 1][k] = __floats2half2_rn(v.z, v.w);
            }
        } else {
            for (int f = tid; f < 640; f += 256) {
                int r = f >> 7;
                int rem = f & 127;
                int kp = rem >> 3, lq = (rem & 7) * 4;
                const float* rb =
                    Rel + (size_t)(r * HH + h) * (KD * KD) + (2 * kp) * KD + lq;
                float4 v0 = *reinterpret_cast<const float4*>(rb);
                float4 v1 = *reinterpret_cast<const float4*>(rb + KD);
                Bs[r][kp][lq + 0] = __floats2half2_rn(v0.x, v1.x);
                Bs[r][kp][lq + 1] = __floats2half2_rn(v0.y, v1.y);
                Bs[r][kp][lq + 2] = __floats2half2_rn(v0.z, v1.z);
                Bs[r][kp][lq + 3] = __floats2half2_rn(v0.w, v1.w);
            }
        }
    }
    __syncthreads();

    uint32_t a[2][2][4];
#pragma unroll
    for (int ks = 0; ks < 2; ks++) {
        int kp0 = ks * 8 + tig;
#pragma unroll
        for (int mt = 0; mt < 2; mt++) {
            int mb = wm * 32 + mt * 16 + grp;
            a[ks][mt][0] = h2u(As[kp0][mb]);
            a[ks][mt][1] = h2u(As[kp0][mb + 8]);
            a[ks][mt][2] = h2u(As[kp0 + 4][mb]);
            a[ks][mt][3] = h2u(As[kp0 + 4][mb + 8]);
        }
    }

    for (int r = 0; r < RR; r++) {
        const float scale =
            which ? 1.f : prior[r * HH + h] * 0.17677669529663688f;
        float acc[2][2][4];
#pragma unroll
        for (int i = 0; i < 2; i++)
#pragma unroll
            for (int j = 0; j < 2; j++)
#pragma unroll
                for (int k = 0; k < 4; k++) acc[i][j][k] = 0.f;
#pragma unroll
        for (int ks = 0; ks < 2; ks++) {
            int kp0 = ks * 8 + tig;
            uint32_t b[2][2];
#pragma unroll
            for (int nt = 0; nt < 2; nt++) {
                int nb = wn * 16 + nt * 8 + grp;
                b[nt][0] = h2u(Bs[r][kp0][nb]);
                b[nt][1] = h2u(Bs[r][kp0 + 4][nb]);
            }
#pragma unroll
            for (int mt = 0; mt < 2; mt++)
#pragma unroll
                for (int nt = 0; nt < 2; nt++)
                    mma_f16(acc[mt][nt], a[ks][mt], b[nt]);
        }
        __half* Or = Out + (size_t)r * NN * DD;
#pragma unroll
        for (int mt = 0; mt < 2; mt++) {
            int nr0 = nbase + wm * 32 + mt * 16 + grp;
            int nr1 = nr0 + 8;
#pragma unroll
            for (int nt = 0; nt < 2; nt++) {
                int col = h * KD + wn * 16 + nt * 8 + tig * 2;
                if (nr0 < NN)
                    *reinterpret_cast<__half2*>(Or + (size_t)nr0 * DD + col) =
                        __floats2half2_rn(acc[mt][nt][0] * scale,
                                          acc[mt][nt][1] * scale);
                if (nr1 < NN)
                    *reinterpret_cast<__half2*>(Or + (size_t)nr1 * DD + col) =
                        __floats2half2_rn(acc[mt][nt][2] * scale,
                                          acc[mt][nt][3] * scale);
            }
        }
    }
}

// ---------------- fused edge phase: one warp per destination ---------------
__global__ __launch_bounds__(256) void k_edge() {
    __shared__ __half sQt[8][RR][256];
    int gw = (blockIdx.x * 256 + threadIdx.x) >> 5;
    if (gw >= NN) return;
    const int w = (threadIdx.x >> 5) & 7;
    const int lane = threadIdx.x & 31;
    const int dst = gw;
    const int s0 = g_start[dst], s1 = g_start[dst + 1];

#pragma unroll
    for (int r = 0; r < RR; r++) {
        float4 q = __ldcs(reinterpret_cast<const float4*>(
            g_Qt + ((size_t)r * NN + dst) * DD + lane * 8));
        *reinterpret_cast<float4*>(&sQt[w][r][lane * 8]) = q;
    }
    // no sync: each lane reads only its own slot

    float ssA = 0.f, ssB = 0.f;
    float aA0 = 0.f, aA1 = 0.f, aA2 = 0.f, aA3 = 0.f;
    float aA4 = 0.f, aA5 = 0.f, aA6 = 0.f, aA7 = 0.f;
    float aB0 = 0.f, aB1 = 0.f, aB2 = 0.f, aB3 = 0.f;
    float aB4 = 0.f, aB5 = 0.f, aB6 = 0.f, aB7 = 0.f;

    int i = s0;
    for (; i + 2 <= s1; i += 2) {
        int pk0 = __ldcs(g_epack + i);
        int pk1 = __ldcs(g_epack + i + 1);
        int r0 = ((unsigned)pk0) >> 24, r1 = ((unsigned)pk1) >> 24;
        size_t ko0 = (size_t)(pk0 & 0xFFFFFF) * DD + lane * 8;
        size_t ko1 = (size_t)(pk1 & 0xFFFFFF) * DD + lane * 8;
        float4 kraw0 = *reinterpret_cast<const float4*>(g_Kn + ko0);
        float4 kraw1 = *reinterpret_cast<const float4*>(g_Kn + ko1);
        float4 mraw0 =
            *reinterpret_cast<const float4*>(g_MtN + (size_t)r0 * NN * DD + ko0);
        float4 mraw1 =
            *reinterpret_cast<const float4*>(g_MtN + (size_t)r1 * NN * DD + ko1);
        float4 qraw0 = *reinterpret_cast<const float4*>(&sQt[w][r0][lane * 8]);
        float4 qraw1 = *reinterpret_cast<const float4*>(&sQt[w][r1][lane * 8]);

        const __half2* qh0 = reinterpret_cast<const __half2*>(&qraw0);
        const __half2* qh1 = reinterpret_cast<const __half2*>(&qraw1);
        const __half2* kh0 = reinterpret_cast<const __half2*>(&kraw0);
        const __half2* kh1 = reinterpret_cast<const __half2*>(&kraw1);
        float d0 = 0.f, d1 = 0.f;
#pragma unroll
        for (int j = 0; j < 4; j++) {
            float2 q0 = __half22float2(qh0[j]);
            float2 k0 = __half22float2(kh0[j]);
            float2 q1 = __half22float2(qh1[j]);
            float2 k1 = __half22float2(kh1[j]);
            d0 += q0.x * k0.x + q0.y * k0.y;
            d1 += q1.x * k1.x + q1.y * k1.y;
        }
        d0 += __shfl_xor_sync(0xffffffffu, d0, 1);
        d1 += __shfl_xor_sync(0xffffffffu, d1, 1);
        d0 += __shfl_xor_sync(0xffffffffu, d0, 2);
        d1 += __shfl_xor_sync(0xffffffffu, d1, 2);
        float ex0 = __expf(d0);
        float ex1 = __expf(d1);
        ssA += ex0;
        ssB += ex1;
        const __half2* mh0 = reinterpret_cast<const __half2*>(&mraw0);
        const __half2* mh1 = reinterpret_cast<const __half2*>(&mraw1);
        float2 m00 = __half22float2(mh0[0]), m01 = __half22float2(mh0[1]);
        float2 m02 = __half22float2(mh0[2]), m03 = __half22float2(mh0[3]);
        float2 m10 = __half22float2(mh1[0]), m11 = __half22float2(mh1[1]);
        float2 m12 = __half22float2(mh1[2]), m13 = __half22float2(mh1[3]);
        aA0 += ex0 * m00.x; aA1 += ex0 * m00.y;
        aA2 += ex0 * m01.x; aA3 += ex0 * m01.y;
        aA4 += ex0 * m02.x; aA5 += ex0 * m02.y;
        aA6 += ex0 * m03.x; aA7 += ex0 * m03.y;
        aB0 += ex1 * m10.x; aB1 += ex1 * m10.y;
        aB2 += ex1 * m11.x; aB3 += ex1 * m11.y;
        aB4 += ex1 * m12.x; aB5 += ex1 * m12.y;
        aB6 += ex1 * m13.x; aB7 += ex1 * m13.y;
    }
    if (i < s1) {
        int pk = __ldcs(g_epack + i);
        int r = ((unsigned)pk) >> 24;
        size_t ko = (size_t)(pk & 0xFFFFFF) * DD + lane * 8;
        float4 kraw = *reinterpret_cast<const float4*>(g_Kn + ko);
        float4 mraw =
            *reinterpret_cast<const float4*>(g_MtN + (size_t)r * NN * DD + ko);
        float4 qraw = *reinterpret_cast<const float4*>(&sQt[w][r][lane * 8]);
        const __half2* qh = reinterpret_cast<const __half2*>(&qraw);
        const __half2* kh = reinterpret_cast<const __half2*>(&kraw);
        float d = 0.f;
#pragma unroll
        for (int j = 0; j < 4; j++) {
            float2 q = __half22float2(qh[j]);
            float2 k = __half22float2(kh[j]);
            d += q.x * k.x + q.y * k.y;
        }
        d += __shfl_xor_sync(0xffffffffu, d, 1);
        d += __shfl_xor_sync(0xffffffffu, d, 2);
        float ex = __expf(d);
        ssA += ex;
        const __half2* mh = reinterpret_cast<const __half2*>(&mraw);
        float2 m0 = __half22float2(mh[0]), m1 = __half22float2(mh[1]);
        float2 m2 = __half22float2(mh[2]), m3 = __half22float2(mh[3]);
        aA0 += ex * m0.x; aA1 += ex * m0.y; aA2 += ex * m1.x; aA3 += ex * m1.y;
        aA4 += ex * m2.x; aA5 += ex * m2.y; aA6 += ex * m3.x; aA7 += ex * m3.y;
    }
    float ssum = ssA + ssB;
    float inv = (ssum > 0.f) ? 1.f / ssum : 0.f;
    float4* o = reinterpret_cast<float4*>(g_aggr + (size_t)dst * DD + lane * 8);
    __stcs(o, make_float4((aA0 + aB0) * inv, (aA1 + aB1) * inv,
                          (aA2 + aB2) * inv, (aA3 + aB3) * inv));
    __stcs(o + 1, make_float4((aA4 + aB4) * inv, (aA5 + aB5) * inv,
                              (aA6 + aB6) * inv, (aA7 + aB7) * inv));
}

// ---------------- classifier + log_softmax ---------------------------------
__global__ __launch_bounds__(256) void k_out(const float* __restrict__ Wout,
                                             const float* __restrict__ bout,
                                             float* __restrict__ out) {
    __shared__ float Ws[DD * CC];
    __shared__ float Hs[16][DD];
    int tid = threadIdx.x;
    for (int i = tid; i < DD * CC; i += 256) Ws[i] = Wout[i];
    int nodeBase = blockIdx.x * 16;
    for (int i = tid; i < 16 * 64; i += 256) {
        int row = i >> 6, c4 = i & 63;
        int node = nodeBase + row;
        float4 v = (node < NN)
                       ? *reinterpret_cast<const float4*>(
                             g_hbuf + (size_t)node * DD + c4 * 4)
                       : make_float4(0.f, 0.f, 0.f, 0.f);
        *reinterpret_cast<float4*>(&Hs[row][c4 * 4]) = v;
    }
    __syncthreads();

    int node = nodeBase + (tid >> 4);
    int c = tid & 15;
    float acc = bout[c];
    const float* hrow = &Hs[tid >> 4][0];
#pragma unroll 8
    for (int k = 0; k < DD; k++) acc += hrow[k] * Ws[k * CC + c];

    float m = acc;
#pragma unroll
    for (int off = 8; off; off >>= 1)
        m = fmaxf(m, __shfl_xor_sync(0xffffffffu, m, off, 16));
    float ee = expf(acc - m);
    float s = ee;
#pragma unroll
    for (int off = 8; off; off >>= 1)
        s += __shfl_xor_sync(0xffffffffu, s, off, 16);
    if (node < NN) out[(size_t)node * CC + c] = acc - m - logf(s);
}

// ---------------- launcher --------------------------------------------------
extern "C" void kernel_launch(void* const* d_in, const int* in_sizes, int n_in,
                              void* d_out, int out_size) {
    const float* x = (const float*)d_in[0];
    const int* ei = (const int*)d_in[1];
    const int* nt = (const int*)d_in[2];
    const int* et = (const int*)d_in[3];
    const float* Wk = (const float*)d_in[4];
    const float* bk = (const float*)d_in[5];
    const float* Wq = (const float*)d_in[6];
    const float* bq = (const float*)d_in[7];
    const float* Wv = (const float*)d_in[8];
    const float* bv = (const float*)d_in[9];
    const float* Wa = (const float*)d_in[10];
    const float* ba = (const float*)d_in[11];
    const float* prior = (const float*)d_in[12];
    const float* rel_att = (const float*)d_in[13];
    const float* rel_msg = (const float*)d_in[14];
    const float* Wout = (const float*)d_in[15];
    const float* bout = (const float*)d_in[16];
    float* out = (float*)d_out;

    // fork: edge-sorting chain runs on side stream, overlapped with the
    // node bucketing + projection/transform GEMMs on the main stream.
    // g_deg starts zeroed (static init) and k_scanE re-zeroes it each call.
    cudaEventRecord(g_evFork, 0);
    cudaStreamWaitEvent(g_s2, g_evFork, 0);
    k_countE<<<(EE + 255) / 256, 256, 0, g_s2>>>(ei);
    k_scanE<<<1, 1024, 0, g_s2>>>();
    k_placeE<<<(EE + 255) / 256, 256, 0, g_s2>>>(ei, et);
    cudaEventRecord(g_evJoin, g_s2);

    // main stream: multi-block node bucketing with aggregated atomics
    k_countN<<<(NN + 511) / 512, 512>>>(nt);
    k_offsets<<<1, 32>>>();
    k_scatterN<<<(NN + 511) / 512, 512>>>(nt);

    dim3 gKQV((NN + 127) / 128, DD / 64, 3 * TT);
    k_typed_kqv<<<gKQV, 256>>>(x, Wk, bk, Wq, bq, Wv, bv);

    dim3 gRel((NN + 127) / 128, HH, 2);
    k_rel_mma<<<gRel, 256>>>(rel_att, rel_msg, prior);

    // join: edge order must be ready before k_edge
    cudaStreamWaitEvent(0, g_evJoin, 0);
    k_edge<<<(NN * 32 + 255) / 256, 256>>>();

    dim3 gUpd((NN + 127) / 128, DD / 64, TT);
    k_typed_upd<<<gUpd, 256>>>(x, Wa, ba);

    k_out<<<(NN + 15) / 16, 256>>>(Wout, bout, out);
}

// round 17
// speedup vs baseline: 1.0715x; 1.0004x over previous
#include <cuda_runtime.h>
#include <cuda_fp16.h>
#include <math.h>
#include <stdint.h>

#define NN 20000
#define EE 320000
#define DD 256
#define HH 8
#define KD 32
#define TT 3
#define RR 5
#define CC 16

// ---------------- scratch (static device globals; no allocation) ----------
__device__ __half g_Kn[NN * DD];                 // fp16 keys
__device__ float  g_Qn[NN * DD];                 // fp32 queries
__device__ float  g_Vn[NN * DD];                 // fp32 values
__device__ __half g_Qt[(size_t)RR * NN * DD];    // prior/sqrtK * rel_att^T . Q
__device__ __half g_MtN[(size_t)RR * NN * DD];   // rel_msg transform of V
__device__ float  g_aggr[NN * DD];
__device__ float  g_hbuf[NN * DD];
__device__ int    g_order[NN];
__device__ int    g_cnt[TT];
__device__ int    g_cntTmp[TT];   // zero at load; re-zeroed by k_offsets
__device__ int    g_base[TT];
__device__ int    g_cur[TT];
__device__ int    g_deg[NN];      // zero at load; re-zeroed by k_scanE
__device__ int    g_start[NN + 1];
__device__ int    g_cur2[NN];
__device__ int    g_epack[EE];    // src | (r << 24), sorted by dst

// ---------------- side stream + events for graph fork/join ------------------
static cudaStream_t g_s2;
static cudaEvent_t  g_evFork, g_evJoin;
static const bool g_side_init = [] {
    cudaStreamCreateWithFlags(&g_s2, cudaStreamNonBlocking);
    cudaEventCreateWithFlags(&g_evFork, cudaEventDisableTiming);
    cudaEventCreateWithFlags(&g_evJoin, cudaEventDisableTiming);
    return true;
}();

// ---------------- helpers --------------------------------------------------
__device__ __forceinline__ void mma_f16(float* d, const uint32_t* a,
                                        const uint32_t* b) {
    asm volatile(
        "mma.sync.aligned.m16n8k16.row.col.f32.f16.f16.f32 "
        "{%0,%1,%2,%3}, {%4,%5,%6,%7}, {%8,%9}, {%0,%1,%2,%3};\n"
        : "+f"(d[0]), "+f"(d[1]), "+f"(d[2]), "+f"(d[3])
        : "r"(a[0]), "r"(a[1]), "r"(a[2]), "r"(a[3]), "r"(b[0]), "r"(b[1]));
}

__device__ __forceinline__ uint32_t h2u(const __half2& h) {
    return *reinterpret_cast<const uint32_t*>(&h);
}

// ---------------- node bucketing: 3 kernels, aggregated atomics -------------
__global__ __launch_bounds__(512) void k_countN(const int* __restrict__ nt) {
    __shared__ int c[TT];
    if (threadIdx.x < TT) c[threadIdx.x] = 0;
    __syncthreads();
    int i = blockIdx.x * 512 + threadIdx.x;
    if (i < NN) atomicAdd(&c[nt[i]], 1);
    __syncthreads();
    if (threadIdx.x < TT && c[threadIdx.x])
        atomicAdd(&g_cntTmp[threadIdx.x], c[threadIdx.x]);
}

__global__ void k_offsets() {
    if (threadIdx.x == 0) {
        int s = 0;
        for (int t = 0; t < TT; t++) {
            int c = g_cntTmp[t];
            g_cntTmp[t] = 0;          // re-zero for next replay
            g_cnt[t] = c;
            g_base[t] = s;
            g_cur[t] = s;
            s += c;
        }
    }
}

__global__ __launch_bounds__(512) void k_scatterN(const int* __restrict__ nt) {
    int i = blockIdx.x * 512 + threadIdx.x;
    const int lane = threadIdx.x & 31;
    int t = (i < NN) ? nt[i] : -1;
#pragma unroll
    for (int tt = 0; tt < TT; tt++) {
        unsigned m = __ballot_sync(0xffffffffu, t == tt);
        if (t == tt) {
            int leader = __ffs(m) - 1;
            int posbase = 0;
            if (lane == leader) posbase = atomicAdd(&g_cur[tt], __popc(m));
            posbase = __shfl_sync(m, posbase, leader);
            g_order[posbase + __popc(m & ((1u << lane) - 1))] = i;
        }
    }
}

// ---------------- edge-side setup (side stream) ------------------------------
__global__ void k_countE(const int* __restrict__ ei) {
    int i = blockIdx.x * blockDim.x + threadIdx.x;
    if (i < EE) atomicAdd(&g_deg[ei[EE + i]], 1);
}

__global__ __launch_bounds__(1024) void k_scanE() {
    __shared__ int part[1024];
    const int tid = threadIdx.x;
    const int CH = (NN + 1023) / 1024;
    int base = tid * CH;
    int s = 0;
    for (int j = 0; j < CH; j++)
        if (base + j < NN) s += g_deg[base + j];
    part[tid] = s;
    __syncthreads();
    for (int off = 1; off < 1024; off <<= 1) {
        int v = (tid >= off) ? part[tid - off] : 0;
        __syncthreads();
        part[tid] += v;
        __syncthreads();
    }
    int run = (tid == 0) ? 0 : part[tid - 1];
    for (int j = 0; j < CH; j++) {
        if (base + j < NN) {
            int d = g_deg[base + j];
            g_deg[base + j] = 0;          // re-zero for the next replay
            g_start[base + j] = run;
            g_cur2[base + j] = run;
            run += d;
        }
    }
    if (tid == 1023) g_start[NN] = part[1023];
}

__global__ void k_placeE(const int* __restrict__ ei,
                         const int* __restrict__ et) {
    int i = blockIdx.x * blockDim.x + threadIdx.x;
    if (i < EE) {
        int dst = ei[EE + i];
        int pos = atomicAdd(&g_cur2[dst], 1);
        g_epack[pos] = ei[i] | (et[i] << 24);
    }
}

// ---------------- typed (gathered) linear via fp16 mma, 128x128 tile --------
// Smem tiles __half2 k-pair packed (As[kp][m], Bs[kp][n]); one 32-bit LDS per
// fragment register. 8 warps: wm (4) x wn (2); each warp owns 32m x 64n.
// MODE 0 : Out = X @ W[t] + b[t]
// MODE 3 : Out = elu(g_aggr) @ W[t] + b[t] + x  (residual, float out)
template <int MODE, typename OutT>
__device__ __forceinline__ void typed_gemm_body(
    const float* __restrict__ X, const float* __restrict__ Xres,
    const float* __restrict__ W, const float* __restrict__ bvec,
    OutT* __restrict__ Out, int t, int m0, int n0) {
    const int cnt = g_cnt[t];
    if (m0 >= cnt) return;
    const int base = g_base[t];
    const int tid = threadIdx.x;
    const int lane = tid & 31, wid = tid >> 5;
    const int wm = wid & 3, wn = wid >> 2;
    const int grp = lane >> 2, tig = lane & 3;

    __shared__ __half2 As[16][136];   // [kp][m], row stride 136 (%32 == 8)
    __shared__ __half2 Bs[16][136];   // [kp][n], row stride 136 (%32 == 8)

    const int arow = tid >> 1;
    const int kpbase = (tid & 1) * 8;
    const int acol0 = (tid & 1) * 16;
    const int am = m0 + arow;
    const float* aptr = nullptr;
    if (am < cnt) aptr = X + (size_t)g_order[base + am] * DD + acol0;

    float acc[2][8][4];
#pragma unroll
    for (int i = 0; i < 2; i++)
#pragma unroll
        for (int j = 0; j < 8; j++)
#pragma unroll
            for (int k = 0; k < 4; k++) acc[i][j][k] = 0.f;

    for (int kk = 0; kk < DD; kk += 32) {
#pragma unroll
        for (int j = 0; j < 4; j++) {
            float4 v = make_float4(0.f, 0.f, 0.f, 0.f);
            if (aptr) v = *reinterpret_cast<const float4*>(aptr + kk + j * 4);
            if (MODE == 3) {
                v.x = v.x > 0.f ? v.x : expm1f(v.x);
                v.y = v.y > 0.f ? v.y : expm1f(v.y);
                v.z = v.z > 0.f ? v.z : expm1f(v.z);
                v.w = v.w > 0.f ? v.w : expm1f(v.w);
            }
            As[kpbase + j * 2 + 0][arow] = __floats2half2_rn(v.x, v.y);
            As[kpbase + j * 2 + 1][arow] = __floats2half2_rn(v.z, v.w);
        }
#pragma unroll
        for (int u = 0; u < 2; u++) {
            int f = tid + u * 256;           // 0..511
            int bkp = f >> 5;                // 0..15
            int bnq = (f & 31) * 4;          // 0..124
            float4 v0 = *reinterpret_cast<const float4*>(
                W + (size_t)(kk + 2 * bkp) * DD + n0 + bnq);
            float4 v1 = *reinterpret_cast<const float4*>(
                W + (size_t)(kk + 2 * bkp + 1) * DD + n0 + bnq);
            Bs[bkp][bnq + 0] = __floats2half2_rn(v0.x, v1.x);
            Bs[bkp][bnq + 1] = __floats2half2_rn(v0.y, v1.y);
            Bs[bkp][bnq + 2] = __floats2half2_rn(v0.z, v1.z);
            Bs[bkp][bnq + 3] = __floats2half2_rn(v0.w, v1.w);
        }
        __syncthreads();
#pragma unroll
        for (int ks = 0; ks < 2; ks++) {
            const int kp0 = ks * 8 + tig;
            uint32_t a[2][4], b[8][2];
#pragma unroll
            for (int mt = 0; mt < 2; mt++) {
                int mb = wm * 32 + mt * 16 + grp;
                a[mt][0] = h2u(As[kp0][mb]);
                a[mt][1] = h2u(As[kp0][mb + 8]);
                a[mt][2] = h2u(As[kp0 + 4][mb]);
                a[mt][3] = h2u(As[kp0 + 4][mb + 8]);
            }
#pragma unroll
            for (int nt = 0; nt < 8; nt++) {
                int nb = wn * 64 + nt * 8 + grp;
                b[nt][0] = h2u(Bs[kp0][nb]);
                b[nt][1] = h2u(Bs[kp0 + 4][nb]);
            }
#pragma unroll
            for (int mt = 0; mt < 2; mt++)
#pragma unroll
                for (int nt = 0; nt < 8; nt++)
                    mma_f16(acc[mt][nt], a[mt], b[nt]);
        }
        __syncthreads();
    }

#pragma unroll
    for (int mt = 0; mt < 2; mt++) {
        int mr0 = m0 + wm * 32 + mt * 16 + grp;
        int mr1 = mr0 + 8;
        int node0 = (mr0 < cnt) ? g_order[base + mr0] : -1;
        int node1 = (mr1 < cnt) ? g_order[base + mr1] : -1;
#pragma unroll
        for (int nt = 0; nt < 8; nt++) {
            int col = n0 + wn * 64 + nt * 8 + tig * 2;
            float2 bi = *reinterpret_cast<const float2*>(bvec + col);
            if (node0 >= 0) {
                float o0 = acc[mt][nt][0] + bi.x;
                float o1 = acc[mt][nt][1] + bi.y;
                if (MODE == 3) {
                    float2 rr = *reinterpret_cast<const float2*>(
                        Xres + (size_t)node0 * DD + col);
                    o0 += rr.x; o1 += rr.y;
                }
                OutT* dst = Out + (size_t)node0 * DD + col;
                if (sizeof(OutT) == 2)
                    *reinterpret_cast<__half2*>(dst) = __floats2half2_rn(o0, o1);
                else
                    *reinterpret_cast<float2*>(dst) = make_float2(o0, o1);
            }
            if (node1 >= 0) {
                float o0 = acc[mt][nt][2] + bi.x;
                float o1 = acc[mt][nt][3] + bi.y;
                if (MODE == 3) {
                    float2 rr = *reinterpret_cast<const float2*>(
                        Xres + (size_t)node1 * DD + col);
                    o0 += rr.x; o1 += rr.y;
                }
                OutT* dst = Out + (size_t)node1 * DD + col;
                if (sizeof(OutT) == 2)
                    *reinterpret_cast<__half2*>(dst) = __floats2half2_rn(o0, o1);
                else
                    *reinterpret_cast<float2*>(dst) = make_float2(o0, o1);
            }
        }
    }
}

// fused K/Q/V projection: grid.z = 3*TT (which = z/TT, t = z%TT)
__global__ __launch_bounds__(256) void k_typed_kqv(
    const float* __restrict__ x,
    const float* __restrict__ Wk, const float* __restrict__ bk,
    const float* __restrict__ Wq, const float* __restrict__ bq,
    const float* __restrict__ Wv, const float* __restrict__ bv) {
    const int z = blockIdx.z;
    const int which = z / TT;
    const int t = z % TT;
    if (which == 0)
        typed_gemm_body<0, __half>(x, nullptr, Wk + (size_t)t * DD * DD,
                                   bk + t * DD, g_Kn, t, blockIdx.x * 128,
                                   blockIdx.y * 128);
    else if (which == 1)
        typed_gemm_body<0, float>(x, nullptr, Wq + (size_t)t * DD * DD,
                                  bq + t * DD, g_Qn, t, blockIdx.x * 128,
                                  blockIdx.y * 128);
    else
        typed_gemm_body<0, float>(x, nullptr, Wv + (size_t)t * DD * DD,
                                  bv + t * DD, g_Vn, t, blockIdx.x * 128,
                                  blockIdx.y * 128);
}

// update: g_hbuf = elu(g_aggr) @ Wa[t] + ba[t] + x
__global__ __launch_bounds__(256) void k_typed_upd(
    const float* __restrict__ x, const float* __restrict__ Wa,
    const float* __restrict__ ba) {
    const int t = blockIdx.z;
    typed_gemm_body<3, float>(g_aggr, x, Wa + (size_t)t * DD * DD, ba + t * DD,
                              g_hbuf, t, blockIdx.x * 128, blockIdx.y * 128);
}

// ---------------- Qt / MtN transforms via fp16 mma, fp16 output -------------
// z=0: g_Qt [r,n,h,k] = prh * sum_l rel_att[r,h,k,l] * Qn[n,h,l]  (transposed B)
// z=1: g_MtN[r,n,h,l] = sum_k Vn[n,h,k] * rel_msg[r,h,k,l]        (natural B)
__global__ __launch_bounds__(256) void k_rel_mma(
    const float* __restrict__ rel_att, const float* __restrict__ rel_msg,
    const float* __restrict__ prior) {
    const int h = blockIdx.y;
    const int which = blockIdx.z;
    const float* In = which ? g_Vn : g_Qn;
    const float* Rel = which ? rel_msg : rel_att;
    __half* Out = which ? g_MtN : g_Qt;
    const int nbase = blockIdx.x * 128;
    const int tid = threadIdx.x;
    const int lane = tid & 31, wid = tid >> 5;
    const int wm = wid & 3, wn = wid >> 2;
    const int grp = lane >> 2, tig = lane & 3;

    __shared__ __half2 As[16][136];     // [kp][m]
    __shared__ __half2 Bs[5][16][40];   // [r][kp][n], row stride 40 (%32 == 8)

    {
        int arow = tid >> 1;
        int kpbase = (tid & 1) * 8;
        int acol0 = (tid & 1) * 16;
        int node = nbase + arow;
        const float* ap = (node < NN)
                              ? In + (size_t)node * DD + h * KD + acol0
                              : nullptr;
#pragma unroll
        for (int j = 0; j < 4; j++) {
            float4 v = ap ? *reinterpret_cast<const float4*>(ap + j * 4)
                          : make_float4(0.f, 0.f, 0.f, 0.f);
            As[kpbase + j * 2 + 0][arow] = __floats2half2_rn(v.x, v.y);
            As[kpbase + j * 2 + 1][arow] = __floats2half2_rn(v.z, v.w);
        }
        if (which == 0) {
#pragma unroll
            for (int j = 0; j < 5; j++) {
                int f = tid + j * 256;
                int r = f >> 8;
                int rem = f & 255;
                int k = rem >> 3, lq = (rem & 7) * 4;
                float4 v = *reinterpret_cast<const float4*>(
                    Rel + (size_t)(r * HH + h) * (KD * KD) + k * KD + lq);
                Bs[r][lq / 2 + 0][k] = __floats2half2_rn(v.x, v.y);
                Bs[r][lq / 2 + 1][k] = __floats2half2_rn(v.z, v.w);
            }
        } else {
            for (int f = tid; f < 640; f += 256) {
                int r = f >> 7;
                int rem = f & 127;
                int kp = rem >> 3, lq = (rem & 7) * 4;
                const float* rb =
                    Rel + (size_t)(r * HH + h) * (KD * KD) + (2 * kp) * KD + lq;
                float4 v0 = *reinterpret_cast<const float4*>(rb);
                float4 v1 = *reinterpret_cast<const float4*>(rb + KD);
                Bs[r][kp][lq + 0] = __floats2half2_rn(v0.x, v1.x);
                Bs[r][kp][lq + 1] = __floats2half2_rn(v0.y, v1.y);
                Bs[r][kp][lq + 2] = __floats2half2_rn(v0.z, v1.z);
                Bs[r][kp][lq + 3] = __floats2half2_rn(v0.w, v1.w);
            }
        }
    }
    __syncthreads();

    uint32_t a[2][2][4];
#pragma unroll
    for (int ks = 0; ks < 2; ks++) {
        int kp0 = ks * 8 + tig;
#pragma unroll
        for (int mt = 0; mt < 2; mt++) {
            int mb = wm * 32 + mt * 16 + grp;
            a[ks][mt][0] = h2u(As[kp0][mb]);
            a[ks][mt][1] = h2u(As[kp0][mb + 8]);
            a[ks][mt][2] = h2u(As[kp0 + 4][mb]);
            a[ks][mt][3] = h2u(As[kp0 + 4][mb + 8]);
        }
    }

    for (int r = 0; r < RR; r++) {
        const float scale =
            which ? 1.f : prior[r * HH + h] * 0.17677669529663688f;
        float acc[2][2][4];
#pragma unroll
        for (int i = 0; i < 2; i++)
#pragma unroll
            for (int j = 0; j < 2; j++)
#pragma unroll
                for (int k = 0; k < 4; k++) acc[i][j][k] = 0.f;
#pragma unroll
        for (int ks = 0; ks < 2; ks++) {
            int kp0 = ks * 8 + tig;
            uint32_t b[2][2];
#pragma unroll
            for (int nt = 0; nt < 2; nt++) {
                int nb = wn * 16 + nt * 8 + grp;
                b[nt][0] = h2u(Bs[r][kp0][nb]);
                b[nt][1] = h2u(Bs[r][kp0 + 4][nb]);
            }
#pragma unroll
            for (int mt = 0; mt < 2; mt++)
#pragma unroll
                for (int nt = 0; nt < 2; nt++)
                    mma_f16(acc[mt][nt], a[ks][mt], b[nt]);
        }
        __half* Or = Out + (size_t)r * NN * DD;
#pragma unroll
        for (int mt = 0; mt < 2; mt++) {
            int nr0 = nbase + wm * 32 + mt * 16 + grp;
            int nr1 = nr0 + 8;
#pragma unroll
            for (int nt = 0; nt < 2; nt++) {
                int col = h * KD + wn * 16 + nt * 8 + tig * 2;
                if (nr0 < NN)
                    *reinterpret_cast<__half2*>(Or + (size_t)nr0 * DD + col) =
                        __floats2half2_rn(acc[mt][nt][0] * scale,
                                          acc[mt][nt][1] * scale);
                if (nr1 < NN)
                    *reinterpret_cast<__half2*>(Or + (size_t)nr1 * DD + col) =
                        __floats2half2_rn(acc[mt][nt][2] * scale,
                                          acc[mt][nt][3] * scale);
            }
        }
    }
}

// ---------------- fused edge phase: one warp per destination ---------------
__global__ __launch_bounds__(256) void k_edge() {
    __shared__ __half sQt[8][RR][256];
    int gw = (blockIdx.x * 256 + threadIdx.x) >> 5;
    if (gw >= NN) return;
    const int w = (threadIdx.x >> 5) & 7;
    const int lane = threadIdx.x & 31;
    const int dst = gw;
    const int s0 = g_start[dst], s1 = g_start[dst + 1];

#pragma unroll
    for (int r = 0; r < RR; r++) {
        float4 q = __ldcs(reinterpret_cast<const float4*>(
            g_Qt + ((size_t)r * NN + dst) * DD + lane * 8));
        *reinterpret_cast<float4*>(&sQt[w][r][lane * 8]) = q;
    }
    // no sync: each lane reads only its own slot

    float ssA = 0.f, ssB = 0.f;
    float aA0 = 0.f, aA1 = 0.f, aA2 = 0.f, aA3 = 0.f;
    float aA4 = 0.f, aA5 = 0.f, aA6 = 0.f, aA7 = 0.f;
    float aB0 = 0.f, aB1 = 0.f, aB2 = 0.f, aB3 = 0.f;
    float aB4 = 0.f, aB5 = 0.f, aB6 = 0.f, aB7 = 0.f;

    int i = s0;
    for (; i + 2 <= s1; i += 2) {
        int pk0 = __ldcs(g_epack + i);
        int pk1 = __ldcs(g_epack + i + 1);
        int r0 = ((unsigned)pk0) >> 24, r1 = ((unsigned)pk1) >> 24;
        size_t ko0 = (size_t)(pk0 & 0xFFFFFF) * DD + lane * 8;
        size_t ko1 = (size_t)(pk1 & 0xFFFFFF) * DD + lane * 8;
        float4 kraw0 = *reinterpret_cast<const float4*>(g_Kn + ko0);
        float4 kraw1 = *reinterpret_cast<const float4*>(g_Kn + ko1);
        float4 mraw0 =
            *reinterpret_cast<const float4*>(g_MtN + (size_t)r0 * NN * DD + ko0);
        float4 mraw1 =
            *reinterpret_cast<const float4*>(g_MtN + (size_t)r1 * NN * DD + ko1);
        float4 qraw0 = *reinterpret_cast<const float4*>(&sQt[w][r0][lane * 8]);
        float4 qraw1 = *reinterpret_cast<const float4*>(&sQt[w][r1][lane * 8]);

        const __half2* qh0 = reinterpret_cast<const __half2*>(&qraw0);
        const __half2* qh1 = reinterpret_cast<const __half2*>(&qraw1);
        const __half2* kh0 = reinterpret_cast<const __half2*>(&kraw0);
        const __half2* kh1 = reinterpret_cast<const __half2*>(&kraw1);
        float d0 = 0.f, d1 = 0.f;
#pragma unroll
        for (int j = 0; j < 4; j++) {
            float2 q0 = __half22float2(qh0[j]);
            float2 k0 = __half22float2(kh0[j]);
            float2 q1 = __half22float2(qh1[j]);
            float2 k1 = __half22float2(kh1[j]);
            d0 += q0.x * k0.x + q0.y * k0.y;
            d1 += q1.x * k1.x + q1.y * k1.y;
        }
        d0 += __shfl_xor_sync(0xffffffffu, d0, 1);
        d1 += __shfl_xor_sync(0xffffffffu, d1, 1);
        d0 += __shfl_xor_sync(0xffffffffu, d0, 2);
        d1 += __shfl_xor_sync(0xffffffffu, d1, 2);
        float ex0 = __expf(d0);
        float ex1 = __expf(d1);
        ssA += ex0;
        ssB += ex1;
        const __half2* mh0 = reinterpret_cast<const __half2*>(&mraw0);
        const __half2* mh1 = reinterpret_cast<const __half2*>(&mraw1);
        float2 m00 = __half22float2(mh0[0]), m01 = __half22float2(mh0[1]);
        float2 m02 = __half22float2(mh0[2]), m03 = __half22float2(mh0[3]);
        float2 m10 = __half22float2(mh1[0]), m11 = __half22float2(mh1[1]);
        float2 m12 = __half22float2(mh1[2]), m13 = __half22float2(mh1[3]);
        aA0 += ex0 * m00.x; aA1 += ex0 * m00.y;
        aA2 += ex0 * m01.x; aA3 += ex0 * m01.y;
        aA4 += ex0 * m02.x; aA5 += ex0 * m02.y;
        aA6 += ex0 * m03.x; aA7 += ex0 * m03.y;
        aB0 += ex1 * m10.x; aB1 += ex1 * m10.y;
        aB2 += ex1 * m11.x; aB3 += ex1 * m11.y;
        aB4 += ex1 * m12.x; aB5 += ex1 * m12.y;
        aB6 += ex1 * m13.x; aB7 += ex1 * m13.y;
    }
    if (i < s1) {
        int pk = __ldcs(g_epack + i);
        int r = ((unsigned)pk) >> 24;
        size_t ko = (size_t)(pk & 0xFFFFFF) * DD + lane * 8;
        float4 kraw = *reinterpret_cast<const float4*>(g_Kn + ko);
        float4 mraw =
            *reinterpret_cast<const float4*>(g_MtN + (size_t)r * NN * DD + ko);
        float4 qraw = *reinterpret_cast<const float4*>(&sQt[w][r][lane * 8]);
        const __half2* qh = reinterpret_cast<const __half2*>(&qraw);
        const __half2* kh = reinterpret_cast<const __half2*>(&kraw);
        float d = 0.f;
#pragma unroll
        for (int j = 0; j < 4; j++) {
            float2 q = __half22float2(qh[j]);
            float2 k = __half22float2(kh[j]);
            d += q.x * k.x + q.y * k.y;
        }
        d += __shfl_xor_sync(0xffffffffu, d, 1);
        d += __shfl_xor_sync(0xffffffffu, d, 2);
        float ex = __expf(d);
        ssA += ex;
        const __half2* mh = reinterpret_cast<const __half2*>(&mraw);
        float2 m0 = __half22float2(mh[0]), m1 = __half22float2(mh[1]);
        float2 m2 = __half22float2(mh[2]), m3 = __half22float2(mh[3]);
        aA0 += ex * m0.x; aA1 += ex * m0.y; aA2 += ex * m1.x; aA3 += ex * m1.y;
        aA4 += ex * m2.x; aA5 += ex * m2.y; aA6 += ex * m3.x; aA7 += ex * m3.y;
    }
    float ssum = ssA + ssB;
    float inv = (ssum > 0.f) ? 1.f / ssum : 0.f;
    float4* o = reinterpret_cast<float4*>(g_aggr + (size_t)dst * DD + lane * 8);
    __stcs(o, make_float4((aA0 + aB0) * inv, (aA1 + aB1) * inv,
                          (aA2 + aB2) * inv, (aA3 + aB3) * inv));
    __stcs(o + 1, make_float4((aA4 + aB4) * inv, (aA5 + aB5) * inv,
                              (aA6 + aB6) * inv, (aA7 + aB7) * inv));
}

// ---------------- classifier + log_softmax ---------------------------------
__global__ __launch_bounds__(256) void k_out(const float* __restrict__ Wout,
                                             const float* __restrict__ bout,
                                             float* __restrict__ out) {
    __shared__ float Ws[DD * CC];
    __shared__ float Hs[16][DD];
    int tid = threadIdx.x;
    for (int i = tid; i < DD * CC; i += 256) Ws[i] = Wout[i];
    int nodeBase = blockIdx.x * 16;
    for (int i = tid; i < 16 * 64; i += 256) {
        int row = i >> 6, c4 = i & 63;
        int node = nodeBase + row;
        float4 v = (node < NN)
                       ? *reinterpret_cast<const float4*>(
                             g_hbuf + (size_t)node * DD + c4 * 4)
                       : make_float4(0.f, 0.f, 0.f, 0.f);
        *reinterpret_cast<float4*>(&Hs[row][c4 * 4]) = v;
    }
    __syncthreads();

    int node = nodeBase + (tid >> 4);
    int c = tid & 15;
    float acc = bout[c];
    const float* hrow = &Hs[tid >> 4][0];
#pragma unroll 8
    for (int k = 0; k < DD; k++) acc += hrow[k] * Ws[k * CC + c];

    float m = acc;
#pragma unroll
    for (int off = 8; off; off >>= 1)
        m = fmaxf(m, __shfl_xor_sync(0xffffffffu, m, off, 16));
    float ee = expf(acc - m);
    float s = ee;
#pragma unroll
    for (int off = 8; off; off >>= 1)
        s += __shfl_xor_sync(0xffffffffu, s, off, 16);
    if (node < NN) out[(size_t)node * CC + c] = acc - m - logf(s);
}

// ---------------- launcher --------------------------------------------------
extern "C" void kernel_launch(void* const* d_in, const int* in_sizes, int n_in,
                              void* d_out, int out_size) {
    const float* x = (const float*)d_in[0];
    const int* ei = (const int*)d_in[1];
    const int* nt = (const int*)d_in[2];
    const int* et = (const int*)d_in[3];
    const float* Wk = (const float*)d_in[4];
    const float* bk = (const float*)d_in[5];
    const float* Wq = (const float*)d_in[6];
    const float* bq = (const float*)d_in[7];
    const float* Wv = (const float*)d_in[8];
    const float* bv = (const float*)d_in[9];
    const float* Wa = (const float*)d_in[10];
    const float* ba = (const float*)d_in[11];
    const float* prior = (const float*)d_in[12];
    const float* rel_att = (const float*)d_in[13];
    const float* rel_msg = (const float*)d_in[14];
    const float* Wout = (const float*)d_in[15];
    const float* bout = (const float*)d_in[16];
    float* out = (float*)d_out;

    // fork: edge-sorting chain runs on side stream, overlapped with the
    // node bucketing + projection/transform GEMMs on the main stream.
    cudaEventRecord(g_evFork, 0);
    cudaStreamWaitEvent(g_s2, g_evFork, 0);
    k_countE<<<(EE + 255) / 256, 256, 0, g_s2>>>(ei);
    k_scanE<<<1, 1024, 0, g_s2>>>();
    k_placeE<<<(EE + 255) / 256, 256, 0, g_s2>>>(ei, et);
    cudaEventRecord(g_evJoin, g_s2);

    // main stream: multi-block node bucketing with aggregated atomics
    k_countN<<<(NN + 511) / 512, 512>>>(nt);
    k_offsets<<<1, 32>>>();
    k_scatterN<<<(NN + 511) / 512, 512>>>(nt);

    dim3 gKQV((NN + 127) / 128, DD / 128, 3 * TT);
    k_typed_kqv<<<gKQV, 256>>>(x, Wk, bk, Wq, bq, Wv, bv);

    dim3 gRel((NN + 127) / 128, HH, 2);
    k_rel_mma<<<gRel, 256>>>(rel_att, rel_msg, prior);

    // join: edge order must be ready before k_edge
    cudaStreamWaitEvent(0, g_evJoin, 0);
    k_edge<<<(NN * 32 + 255) / 256, 256>>>();

    dim3 gUpd((NN + 127) / 128, DD / 128, TT);
    k_typed_upd<<<gUpd, 256>>>(x, Wa, ba);

    k_out<<<(NN + 15) / 16, 256>>>(Wout, bout, out);
}